// round 1
// baseline (speedup 1.0000x reference)
#include <cuda_runtime.h>
#include <cuda_bf16.h>
#include <math.h>

#define E_    32
#define TOPK  4
#define H_    2048
#define I_    1408
#define GS_   128
#define T_    1024
#define ISH_  2816
#define NPAIR (T_*TOPK)

#define BM 64
#define BN 64
#define BK 32

// ---------------- device scratch (static globals; no allocation) ----------------
__device__ int   g_counts[E_];
__device__ int   g_offsets[E_];
__device__ int   g_cursor[E_];
__device__ int   g_topk_idx[T_][TOPK];
__device__ float g_topk_w[T_][TOPK];
__device__ int   g_pair_token[NPAIR];
__device__ float g_pair_w[NPAIR];
__device__ int   g_pair_pos[T_][TOPK];
__device__ float g_h[(size_t)NPAIR * I_];     // ~23 MB
__device__ float g_y[(size_t)NPAIR * H_];     // ~34 MB
__device__ float g_sh[(size_t)T_ * ISH_];     // ~11.5 MB

// ---------------- small kernels ----------------
__global__ void zero_kernel() {
    int i = threadIdx.x;
    if (i < E_) { g_counts[i] = 0; }
}

__global__ void router_kernel(const float* __restrict__ x, const float* __restrict__ gw) {
    __shared__ float xs[H_];
    __shared__ float part[8][E_];
    __shared__ float scores[E_];
    int t = blockIdx.x;
    for (int h = threadIdx.x; h < H_; h += 256) xs[h] = x[t * H_ + h];
    __syncthreads();
    int e  = threadIdx.x & 31;
    int hh = threadIdx.x >> 5;
    float acc = 0.f;
    for (int h = hh; h < H_; h += 8) acc += xs[h] * gw[h * E_ + e];
    part[hh][e] = acc;
    __syncthreads();
    if (threadIdx.x < E_) {
        float s = 0.f;
        #pragma unroll
        for (int i = 0; i < 8; i++) s += part[i][threadIdx.x];
        scores[threadIdx.x] = 1.f / (1.f + expf(-s));
    }
    __syncthreads();
    if (threadIdx.x == 0) {
        bool used[E_];
        #pragma unroll
        for (int i = 0; i < E_; i++) used[i] = false;
        float v[TOPK]; int id[TOPK];
        float sum = 0.f;
        for (int j = 0; j < TOPK; j++) {
            float best = -1e30f; int bi = 0;
            for (int ee = 0; ee < E_; ee++)
                if (!used[ee] && scores[ee] > best) { best = scores[ee]; bi = ee; }
            used[bi] = true; v[j] = best; id[j] = bi; sum += best;
        }
        float inv = 2.5f / (sum + 1e-20f);
        for (int j = 0; j < TOPK; j++) {
            g_topk_idx[t][j] = id[j];
            g_topk_w[t][j]   = v[j] * inv;
            atomicAdd(&g_counts[id[j]], 1);
        }
    }
}

__global__ void scan_kernel() {
    if (threadIdx.x == 0) {
        int off = 0;
        for (int e = 0; e < E_; e++) {
            g_offsets[e] = off;
            g_cursor[e]  = off;
            off += g_counts[e];
        }
    }
}

__global__ void scatter_kernel() {
    int t = blockIdx.x * blockDim.x + threadIdx.x;
    if (t >= T_) return;
    for (int j = 0; j < TOPK; j++) {
        int e = g_topk_idx[t][j];
        int pos = atomicAdd(&g_cursor[e], 1);
        g_pair_token[pos] = t;
        g_pair_w[pos]     = g_topk_w[t][j];
        g_pair_pos[t][j]  = pos;
    }
}

// ---------------- expert gate/up fused dequant-GEMM + SwiGLU ----------------
// C[m][n] = silu( sum_k X[m][k] Wg[n][k] ) * ( sum_k X[m][k] Wu[n][k] )
__global__ __launch_bounds__(256) void expert_gu_kernel(
    const float* __restrict__ x,
    const int* __restrict__ gq, const int* __restrict__ gz, const float* __restrict__ gs,
    const int* __restrict__ uq, const int* __restrict__ uz, const float* __restrict__ us)
{
    int e   = blockIdx.z;
    int cnt = g_counts[e];
    int m0  = blockIdx.y * BM;
    if (m0 >= cnt) return;
    int off = g_offsets[e];
    int n0  = blockIdx.x * BN;

    __shared__ float As[BM][BK];
    __shared__ float Bg[BK][BN];
    __shared__ float Bu[BK][BN];
    __shared__ int   toks[BM];

    int tid = threadIdx.x;
    if (tid < BM) {
        int m = m0 + tid;
        toks[tid] = (m < cnt) ? g_pair_token[off + m] : 0;
    }

    float accG[4][4] = {}, accU[4][4] = {};
    int tm = (tid >> 4) * 4;
    int tn = (tid & 15) * 4;
    int bn = tid >> 2;     // 0..63: output row within tile
    int bw = tid & 3;      // packed word within BK

    long rowg = (long)e * I_ + (n0 + bn);

    for (int k0 = 0; k0 < H_; k0 += BK) {
        __syncthreads();
        // A tile: 64x32, coalesced by k
        #pragma unroll
        for (int i = 0; i < 8; i++) {
            int idx = tid + i * 256;
            int m = idx >> 5, k = idx & 31;
            As[m][k] = x[(long)toks[m] * H_ + k0 + k];
        }
        // B tiles: decode 4-bit
        {
            int g = k0 / GS_;
            int w = gq[rowg * (H_/8) + (k0 >> 3) + bw];
            float z = (float)gz[rowg * (H_/GS_) + g];
            float s = gs[rowg * (H_/GS_) + g];
            #pragma unroll
            for (int j = 0; j < 8; j++)
                Bg[bw*8 + j][bn] = ((float)((w >> (4*j)) & 0xF) - z) * s;
            w = uq[rowg * (H_/8) + (k0 >> 3) + bw];
            z = (float)uz[rowg * (H_/GS_) + g];
            s = us[rowg * (H_/GS_) + g];
            #pragma unroll
            for (int j = 0; j < 8; j++)
                Bu[bw*8 + j][bn] = ((float)((w >> (4*j)) & 0xF) - z) * s;
        }
        __syncthreads();
        #pragma unroll
        for (int k = 0; k < BK; k++) {
            float a[4];
            #pragma unroll
            for (int i = 0; i < 4; i++) a[i] = As[tm + i][k];
            float4 vg = *(const float4*)&Bg[k][tn];
            float4 vu = *(const float4*)&Bu[k][tn];
            float bg[4] = {vg.x, vg.y, vg.z, vg.w};
            float bu[4] = {vu.x, vu.y, vu.z, vu.w};
            #pragma unroll
            for (int i = 0; i < 4; i++)
                #pragma unroll
                for (int j = 0; j < 4; j++) {
                    accG[i][j] += a[i] * bg[j];
                    accU[i][j] += a[i] * bu[j];
                }
        }
    }
    #pragma unroll
    for (int i = 0; i < 4; i++) {
        int m = m0 + tm + i;
        if (m < cnt) {
            #pragma unroll
            for (int j = 0; j < 4; j++) {
                float g = accG[i][j];
                float hval = g / (1.f + expf(-g)) * accU[i][j];
                g_h[(size_t)(off + m) * I_ + n0 + tn + j] = hval;
            }
        }
    }
}

// ---------------- expert down dequant-GEMM (scaled by routing weight) ----------------
__global__ __launch_bounds__(256) void expert_down_kernel(
    const int* __restrict__ dq, const int* __restrict__ dz, const float* __restrict__ ds)
{
    int e   = blockIdx.z;
    int cnt = g_counts[e];
    int m0  = blockIdx.y * BM;
    if (m0 >= cnt) return;
    int off = g_offsets[e];
    int n0  = blockIdx.x * BN;

    __shared__ float As[BM][BK];
    __shared__ float Bs[BK][BN];
    __shared__ float pw[BM];

    int tid = threadIdx.x;
    if (tid < BM) {
        int m = m0 + tid;
        pw[tid] = (m < cnt) ? g_pair_w[off + m] : 0.f;
    }

    float acc[4][4] = {};
    int tm = (tid >> 4) * 4;
    int tn = (tid & 15) * 4;
    int bn = tid >> 2;
    int bw = tid & 3;
    long rowd = (long)e * H_ + (n0 + bn);

    for (int k0 = 0; k0 < I_; k0 += BK) {
        __syncthreads();
        #pragma unroll
        for (int i = 0; i < 8; i++) {
            int idx = tid + i * 256;
            int m = idx >> 5, k = idx & 31;
            int mr = m0 + m;
            As[m][k] = (mr < cnt) ? g_h[(size_t)(off + mr) * I_ + k0 + k] : 0.f;
        }
        {
            int g = k0 / GS_;
            int w = dq[rowd * (I_/8) + (k0 >> 3) + bw];
            float z = (float)dz[rowd * (I_/GS_) + g];
            float s = ds[rowd * (I_/GS_) + g];
            #pragma unroll
            for (int j = 0; j < 8; j++)
                Bs[bw*8 + j][bn] = ((float)((w >> (4*j)) & 0xF) - z) * s;
        }
        __syncthreads();
        #pragma unroll
        for (int k = 0; k < BK; k++) {
            float a[4];
            #pragma unroll
            for (int i = 0; i < 4; i++) a[i] = As[tm + i][k];
            float4 vb = *(const float4*)&Bs[k][tn];
            float b[4] = {vb.x, vb.y, vb.z, vb.w};
            #pragma unroll
            for (int i = 0; i < 4; i++)
                #pragma unroll
                for (int j = 0; j < 4; j++)
                    acc[i][j] += a[i] * b[j];
        }
    }
    #pragma unroll
    for (int i = 0; i < 4; i++) {
        int m = m0 + tm + i;
        if (m < cnt) {
            float w = pw[tm + i];
            #pragma unroll
            for (int j = 0; j < 4; j++)
                g_y[(size_t)(off + m) * H_ + n0 + tn + j] = w * acc[i][j];
        }
    }
}

// ---------------- shared experts gate/up (dense NN GEMM + SwiGLU) ----------------
__global__ __launch_bounds__(256) void shared_gu_kernel(
    const float* __restrict__ x,
    const float* __restrict__ wgt, const float* __restrict__ wup)
{
    int m0 = blockIdx.y * BM;
    int n0 = blockIdx.x * BN;

    __shared__ float As[BM][BK];
    __shared__ float Bg[BK][BN];
    __shared__ float Bu[BK][BN];

    int tid = threadIdx.x;
    float accG[4][4] = {}, accU[4][4] = {};
    int tm = (tid >> 4) * 4;
    int tn = (tid & 15) * 4;

    for (int k0 = 0; k0 < H_; k0 += BK) {
        __syncthreads();
        #pragma unroll
        for (int i = 0; i < 8; i++) {
            int idx = tid + i * 256;
            int m = idx >> 5, k = idx & 31;
            As[m][k] = x[(long)(m0 + m) * H_ + k0 + k];
        }
        #pragma unroll
        for (int i = 0; i < 8; i++) {
            int idx = tid + i * 256;
            int k = idx >> 6, n = idx & 63;
            Bg[k][n] = wgt[(long)(k0 + k) * ISH_ + n0 + n];
            Bu[k][n] = wup[(long)(k0 + k) * ISH_ + n0 + n];
        }
        __syncthreads();
        #pragma unroll
        for (int k = 0; k < BK; k++) {
            float a[4];
            #pragma unroll
            for (int i = 0; i < 4; i++) a[i] = As[tm + i][k];
            float4 vg = *(const float4*)&Bg[k][tn];
            float4 vu = *(const float4*)&Bu[k][tn];
            float bg[4] = {vg.x, vg.y, vg.z, vg.w};
            float bu[4] = {vu.x, vu.y, vu.z, vu.w};
            #pragma unroll
            for (int i = 0; i < 4; i++)
                #pragma unroll
                for (int j = 0; j < 4; j++) {
                    accG[i][j] += a[i] * bg[j];
                    accU[i][j] += a[i] * bu[j];
                }
        }
    }
    #pragma unroll
    for (int i = 0; i < 4; i++)
        #pragma unroll
        for (int j = 0; j < 4; j++) {
            float g = accG[i][j];
            g_sh[(size_t)(m0 + tm + i) * ISH_ + n0 + tn + j] =
                g / (1.f + expf(-g)) * accU[i][j];
        }
}

// ---------------- shared down GEMM + final combine ----------------
__global__ __launch_bounds__(256) void shared_down_combine_kernel(
    const float* __restrict__ wdn, float* __restrict__ out)
{
    int m0 = blockIdx.y * BM;
    int n0 = blockIdx.x * BN;

    __shared__ float As[BM][BK];
    __shared__ float Bs[BK][BN];

    int tid = threadIdx.x;
    float acc[4][4] = {};
    int tm = (tid >> 4) * 4;
    int tn = (tid & 15) * 4;

    for (int k0 = 0; k0 < ISH_; k0 += BK) {
        __syncthreads();
        #pragma unroll
        for (int i = 0; i < 8; i++) {
            int idx = tid + i * 256;
            int m = idx >> 5, k = idx & 31;
            As[m][k] = g_sh[(size_t)(m0 + m) * ISH_ + k0 + k];
        }
        #pragma unroll
        for (int i = 0; i < 8; i++) {
            int idx = tid + i * 256;
            int k = idx >> 6, n = idx & 63;
            Bs[k][n] = wdn[(long)(k0 + k) * H_ + n0 + n];
        }
        __syncthreads();
        #pragma unroll
        for (int k = 0; k < BK; k++) {
            float a[4];
            #pragma unroll
            for (int i = 0; i < 4; i++) a[i] = As[tm + i][k];
            float4 vb = *(const float4*)&Bs[k][tn];
            float b[4] = {vb.x, vb.y, vb.z, vb.w};
            #pragma unroll
            for (int i = 0; i < 4; i++)
                #pragma unroll
                for (int j = 0; j < 4; j++)
                    acc[i][j] += a[i] * b[j];
        }
    }
    #pragma unroll
    for (int i = 0; i < 4; i++) {
        int t = m0 + tm + i;
        int p0 = g_pair_pos[t][0], p1 = g_pair_pos[t][1];
        int p2 = g_pair_pos[t][2], p3 = g_pair_pos[t][3];
        #pragma unroll
        for (int j = 0; j < 4; j++) {
            int n = n0 + tn + j;
            float v = acc[i][j]
                    + g_y[(size_t)p0 * H_ + n] + g_y[(size_t)p1 * H_ + n]
                    + g_y[(size_t)p2 * H_ + n] + g_y[(size_t)p3 * H_ + n];
            out[(long)t * H_ + n] = v;
        }
    }
}

// ---------------- launch ----------------
extern "C" void kernel_launch(void* const* d_in, const int* in_sizes, int n_in,
                              void* d_out, int out_size)
{
    const float* x   = (const float*)d_in[0];
    const float* gw  = (const float*)d_in[1];
    const int*   gq  = (const int*)  d_in[2];
    const int*   gz  = (const int*)  d_in[3];
    const float* gs  = (const float*)d_in[4];
    const int*   uq  = (const int*)  d_in[5];
    const int*   uz  = (const int*)  d_in[6];
    const float* us  = (const float*)d_in[7];
    const int*   dq  = (const int*)  d_in[8];
    const int*   dz  = (const int*)  d_in[9];
    const float* ds  = (const float*)d_in[10];
    const float* sgw = (const float*)d_in[11];
    const float* suw = (const float*)d_in[12];
    const float* sdw = (const float*)d_in[13];
    float* out = (float*)d_out;

    zero_kernel<<<1, 32>>>();
    router_kernel<<<T_, 256>>>(x, gw);
    scan_kernel<<<1, 32>>>();
    scatter_kernel<<<(T_ + 255) / 256, 256>>>();

    dim3 ggu(I_ / BN, T_ / BM, E_);      // (22, 16, 32)
    expert_gu_kernel<<<ggu, 256>>>(x, gq, gz, gs, uq, uz, us);

    dim3 gdn(H_ / BN, T_ / BM, E_);      // (32, 16, 32)
    expert_down_kernel<<<gdn, 256>>>(dq, dz, ds);

    dim3 gsg(ISH_ / BN, T_ / BM);        // (44, 16)
    shared_gu_kernel<<<gsg, 256>>>(x, sgw, suw);

    dim3 gsd(H_ / BN, T_ / BM);          // (32, 16)
    shared_down_combine_kernel<<<gsd, 256>>>(sdw, out);
}

// round 3
// speedup vs baseline: 1.9354x; 1.9354x over previous
#include <cuda_runtime.h>
#include <cuda_bf16.h>
#include <math.h>
#include <stdint.h>

#define E_    32
#define TOPK  4
#define H_    2048
#define I_    1408
#define GS_   128
#define T_    1024
#define ISH_  2816
#define NPAIR (T_*TOPK)

// ---------------- device scratch ----------------
__device__ int   g_counts[E_];
__device__ int   g_offsets[E_];
__device__ int   g_cursor[E_];
__device__ int   g_topk_idx[T_][TOPK];
__device__ float g_topk_w[T_][TOPK];
__device__ int   g_pair_token[NPAIR];
__device__ float g_pair_w[NPAIR];
__device__ int   g_pair_pos[T_][TOPK];
__device__ float g_h[(size_t)NPAIR * I_];
__device__ float g_y[(size_t)NPAIR * H_];
__device__ float g_sh[(size_t)T_ * ISH_];
__device__ float g_sgwT[(size_t)ISH_ * H_];   // [ISH][H]
__device__ float g_suwT[(size_t)ISH_ * H_];   // [ISH][H]
__device__ float g_sdwT[(size_t)H_ * ISH_];   // [H][ISH]

// ---------------- helpers ----------------
__device__ __forceinline__ float to_tf32(float x) {
    float r;
    asm("cvt.rna.tf32.f32 %0, %1;" : "=f"(r) : "f"(x));
    return r;
}
__device__ __forceinline__ float4 cvt4(float4 v) {
    v.x = to_tf32(v.x); v.y = to_tf32(v.y); v.z = to_tf32(v.z); v.w = to_tf32(v.w);
    return v;
}
// 4 codes from packed word starting at bit sh, dequant to tf32
__device__ __forceinline__ float4 dq4(unsigned w, int sh, float s, float zs) {
    float4 v;
    v.x = to_tf32(fmaf((float)((w >> (sh + 0 )) & 15), s, -zs));
    v.y = to_tf32(fmaf((float)((w >> (sh + 4 )) & 15), s, -zs));
    v.z = to_tf32(fmaf((float)((w >> (sh + 8 )) & 15), s, -zs));
    v.w = to_tf32(fmaf((float)((w >> (sh + 12)) & 15), s, -zs));
    return v;
}
// m16n8k8 tf32 mma, D += A*B
__device__ __forceinline__ void mma8(float* d, const unsigned* a, const unsigned* b) {
    asm volatile("mma.sync.aligned.m16n8k8.row.col.f32.tf32.tf32.f32 "
        "{%0,%1,%2,%3},{%4,%5,%6,%7},{%8,%9},{%0,%1,%2,%3};\n"
        : "+f"(d[0]), "+f"(d[1]), "+f"(d[2]), "+f"(d[3])
        : "r"(a[0]), "r"(a[1]), "r"(a[2]), "r"(a[3]), "r"(b[0]), "r"(b[1]));
}
__device__ __forceinline__ float silu_mul(float g, float u) {
    return g / (1.f + __expf(-g)) * u;
}

// smem layout (floats): [0..255] aux, then 2 buffers of 8192 floats each.
// A tile (128x32): [kfrag4][mfrag8][plane4][lane32]
__device__ __forceinline__ int aoff(int buf, int kf, int mf, int p) {
    return 256 + buf * 8192 + ((kf * 8 + mf) * 4 + p) * 32;
}
// B tile 64 rows (gu kernels), sel=0 gate / 1 up: [kfrag4][nfrag8][plane2][lane32]
__device__ __forceinline__ int boff_gu(int buf, int kf, int nf, int p, int sel) {
    return 256 + buf * 8192 + 4096 + sel * 2048 + ((kf * 8 + nf) * 2 + p) * 32;
}
// B tile 128 rows (down kernels): [kfrag4][nfrag16][plane2][lane32]
__device__ __forceinline__ int boff_dn(int buf, int kf, int nf, int p) {
    return 256 + buf * 8192 + 4096 + ((kf * 16 + nf) * 2 + p) * 32;
}
#define SMEM_BYTES 66560

// ---------------- small kernels ----------------
__global__ void zero_kernel() {
    int i = threadIdx.x;
    if (i < E_) g_counts[i] = 0;
}

__global__ void router_kernel(const float* __restrict__ x, const float* __restrict__ gw) {
    __shared__ float xs[H_];
    __shared__ float part[8][E_];
    __shared__ float scores[E_];
    int t = blockIdx.x;
    for (int h = threadIdx.x; h < H_; h += 256) xs[h] = x[t * H_ + h];
    __syncthreads();
    int e = threadIdx.x & 31;
    int hh = threadIdx.x >> 5;
    float acc = 0.f;
    for (int h = hh; h < H_; h += 8) acc += xs[h] * gw[h * E_ + e];
    part[hh][e] = acc;
    __syncthreads();
    if (threadIdx.x < E_) {
        float s = 0.f;
        #pragma unroll
        for (int i = 0; i < 8; i++) s += part[i][threadIdx.x];
        scores[threadIdx.x] = 1.f / (1.f + expf(-s));
    }
    __syncthreads();
    if (threadIdx.x == 0) {
        bool used[E_];
        #pragma unroll
        for (int i = 0; i < E_; i++) used[i] = false;
        float v[TOPK]; int id[TOPK];
        float sum = 0.f;
        for (int j = 0; j < TOPK; j++) {
            float best = -1e30f; int bi = 0;
            for (int ee = 0; ee < E_; ee++)
                if (!used[ee] && scores[ee] > best) { best = scores[ee]; bi = ee; }
            used[bi] = true; v[j] = best; id[j] = bi; sum += best;
        }
        float inv = 2.5f / (sum + 1e-20f);
        for (int j = 0; j < TOPK; j++) {
            g_topk_idx[t][j] = id[j];
            g_topk_w[t][j] = v[j] * inv;
            atomicAdd(&g_counts[id[j]], 1);
        }
    }
}

__global__ void scan_kernel() {
    if (threadIdx.x == 0) {
        int off = 0;
        for (int e = 0; e < E_; e++) {
            g_offsets[e] = off; g_cursor[e] = off; off += g_counts[e];
        }
    }
}

__global__ void scatter_kernel() {
    int t = blockIdx.x * blockDim.x + threadIdx.x;
    if (t >= T_) return;
    for (int j = 0; j < TOPK; j++) {
        int e = g_topk_idx[t][j];
        int pos = atomicAdd(&g_cursor[e], 1);
        g_pair_token[pos] = t;
        g_pair_w[pos] = g_topk_w[t][j];
        g_pair_pos[t][j] = pos;
    }
}

// in[R][C] -> out[C][R], tf32-rounded
__global__ void transpose_kernel(const float* __restrict__ in, float* __restrict__ out, int R, int C) {
    __shared__ float tile[32][33];
    int c0 = blockIdx.x * 32, r0 = blockIdx.y * 32;
    for (int i = threadIdx.y; i < 32; i += 8)
        tile[i][threadIdx.x] = in[(size_t)(r0 + i) * C + c0 + threadIdx.x];
    __syncthreads();
    for (int i = threadIdx.y; i < 32; i += 8)
        out[(size_t)(c0 + i) * R + r0 + threadIdx.x] = to_tf32(tile[threadIdx.x][i]);
}

// ================= expert gate/up: h = silu(X Wg^T) * (X Wu^T) =================
// block 128(M) x 64(N), BK=32, 256 threads, warp tile 32x32 (4 M-warps x 2 N-warps)
__global__ __launch_bounds__(256, 1) void expert_gu_mma(
    const float* __restrict__ x,
    const int* __restrict__ gq, const int* __restrict__ gz, const float* __restrict__ gs,
    const int* __restrict__ uq, const int* __restrict__ uz, const float* __restrict__ us)
{
    extern __shared__ float sm[];
    int e = blockIdx.z;
    int cnt = g_counts[e];
    int m0 = blockIdx.y * 128;
    if (m0 >= cnt) return;
    int off = g_offsets[e];
    int n0 = blockIdx.x * 64;
    int tid = threadIdx.x;

    int* toks = (int*)sm;
    if (tid < 128) {
        int m = m0 + tid;
        toks[tid] = (m < cnt) ? g_pair_token[off + m] : 0;
    }
    __syncthreads();

    // fill roles
    int fm = tid & 127, kh = tid >> 7;                   // A: row fm, k-half kh (16 floats)
    const float* xrow = x + (size_t)toks[fm] * H_ + kh * 16;
    int sel = tid >> 7;                                   // 0 gate, 1 up
    int t2 = tid & 127;
    int fn = t2 & 63, bkh = t2 >> 6;                      // B: row fn, k-half bkh
    long rowb = (long)e * I_ + n0 + fn;
    const int*   qr = (sel ? uq : gq) + rowb * (H_ / 8) + bkh * 2;
    const int*   zr = (sel ? uz : gz) + rowb * (H_ / GS_);
    const float* sr = (sel ? us : gs) + rowb * (H_ / GS_);

    int w = tid >> 5, lane = tid & 31;
    int wm = w & 3, wn = w >> 2;

    float accG[2][4][4] = {};
    float accU[2][4][4] = {};

    float4 pa[4]; unsigned pw0, pw1; float ps, pz;
    {
        const float4* xp = (const float4*)xrow;
        pa[0] = xp[0]; pa[1] = xp[1]; pa[2] = xp[2]; pa[3] = xp[3];
        pw0 = (unsigned)qr[0]; pw1 = (unsigned)qr[1];
        ps = sr[0]; pz = (float)zr[0] * ps;
    }

    const int NT = H_ / 32;
    int amf = fm >> 4, ami8 = (fm & 15) >> 3, alb = (fm & 7) * 4;
    int bnf = fn >> 3, blb = (fn & 7) * 4;

    for (int t = 0; t < NT; t++) {
        int buf = t & 1;
        // store A (4 groups of 4 floats)
        #pragma unroll
        for (int g = 0; g < 4; g++) {
            int kf = kh * 2 + (g >> 1);
            int p = ami8 + 2 * (g & 1);
            *(float4*)&sm[aoff(buf, kf, amf, p) + alb] = cvt4(pa[g]);
        }
        // store B (dequant)
        #pragma unroll
        for (int g = 0; g < 4; g++) {
            int kf = bkh * 2 + (g >> 1);
            unsigned wd = (g >> 1) ? pw1 : pw0;
            float4 v = dq4(wd, (g & 1) * 16, ps, pz);
            *(float4*)&sm[boff_gu(buf, kf, bnf, g & 1, sel) + blb] = v;
        }
        __syncthreads();
        if (t + 1 < NT) {
            int k0n = (t + 1) * 32;
            const float4* xp = (const float4*)(xrow + k0n);
            pa[0] = xp[0]; pa[1] = xp[1]; pa[2] = xp[2]; pa[3] = xp[3];
            const int* qp = qr + (k0n >> 3);
            pw0 = (unsigned)qp[0]; pw1 = (unsigned)qp[1];
            int gi = k0n >> 7;
            ps = sr[gi]; pz = (float)zr[gi] * ps;
        }
        // mma
        #pragma unroll
        for (int kf = 0; kf < 4; kf++) {
            unsigned a[2][4], bg[4][2], bu[4][2];
            #pragma unroll
            for (int mf = 0; mf < 2; mf++)
                #pragma unroll
                for (int r = 0; r < 4; r++)
                    a[mf][r] = __float_as_uint(sm[aoff(buf, kf, wm * 2 + mf, r) + lane]);
            #pragma unroll
            for (int nf = 0; nf < 4; nf++)
                #pragma unroll
                for (int r = 0; r < 2; r++) {
                    bg[nf][r] = __float_as_uint(sm[boff_gu(buf, kf, wn * 4 + nf, r, 0) + lane]);
                    bu[nf][r] = __float_as_uint(sm[boff_gu(buf, kf, wn * 4 + nf, r, 1) + lane]);
                }
            #pragma unroll
            for (int mf = 0; mf < 2; mf++)
                #pragma unroll
                for (int nf = 0; nf < 4; nf++) {
                    mma8(accG[mf][nf], a[mf], bg[nf]);
                    mma8(accU[mf][nf], a[mf], bu[nf]);
                }
        }
    }

    // epilogue
    #pragma unroll
    for (int mf = 0; mf < 2; mf++) {
        #pragma unroll
        for (int hh = 0; hh < 2; hh++) {
            int row = wm * 32 + mf * 16 + (lane >> 2) + hh * 8;
            if (m0 + row < cnt) {
                float* orow = g_h + (size_t)(off + m0 + row) * I_ + n0;
                #pragma unroll
                for (int nf = 0; nf < 4; nf++) {
                    int col = wn * 32 + nf * 8 + (lane & 3) * 2;
                    float2 v;
                    v.x = to_tf32(silu_mul(accG[mf][nf][hh * 2],     accU[mf][nf][hh * 2]));
                    v.y = to_tf32(silu_mul(accG[mf][nf][hh * 2 + 1], accU[mf][nf][hh * 2 + 1]));
                    *(float2*)(orow + col) = v;
                }
            }
        }
    }
}

// ================= expert down: y = pw * (h @ Wd^T) =================
// block 128(M) x 128(N), 256 threads, warp tile 64x32 (2 M x 4 N)
__global__ __launch_bounds__(256, 1) void expert_down_mma(
    const int* __restrict__ dq, const int* __restrict__ dz, const float* __restrict__ ds)
{
    extern __shared__ float sm[];
    int e = blockIdx.z;
    int cnt = g_counts[e];
    int m0 = blockIdx.y * 128;
    if (m0 >= cnt) return;
    int off = g_offsets[e];
    int n0 = blockIdx.x * 128;
    int tid = threadIdx.x;

    float* pwv = sm;
    if (tid < 128) {
        int m = m0 + tid;
        pwv[tid] = (m < cnt) ? g_pair_w[off + m] : 0.f;
    }
    __syncthreads();

    int fm = tid & 127, kh = tid >> 7;
    size_t ar = (size_t)off + ((m0 + fm < cnt) ? (m0 + fm) : 0);
    const float* hrow = g_h + ar * I_ + kh * 16;
    int fn = tid & 127, bkh = tid >> 7;
    long rowb = (long)e * H_ + n0 + fn;
    const int*   qr = dq + rowb * (I_ / 8) + bkh * 2;
    const int*   zr = dz + rowb * (I_ / GS_);
    const float* sr = ds + rowb * (I_ / GS_);

    int w = tid >> 5, lane = tid & 31;
    int wm = w & 1, wn = w >> 1;

    float acc[4][4][4] = {};

    float4 pa[4]; unsigned pw0, pw1; float ps, pz;
    {
        const float4* hp = (const float4*)hrow;
        pa[0] = hp[0]; pa[1] = hp[1]; pa[2] = hp[2]; pa[3] = hp[3];
        pw0 = (unsigned)qr[0]; pw1 = (unsigned)qr[1];
        ps = sr[0]; pz = (float)zr[0] * ps;
    }

    const int NT = I_ / 32;  // 44
    int amf = fm >> 4, ami8 = (fm & 15) >> 3, alb = (fm & 7) * 4;
    int bnf = fn >> 3, blb = (fn & 7) * 4;

    for (int t = 0; t < NT; t++) {
        int buf = t & 1;
        #pragma unroll
        for (int g = 0; g < 4; g++) {
            int kf = kh * 2 + (g >> 1);
            int p = ami8 + 2 * (g & 1);
            *(float4*)&sm[aoff(buf, kf, amf, p) + alb] = pa[g];   // already tf32
        }
        #pragma unroll
        for (int g = 0; g < 4; g++) {
            int kf = bkh * 2 + (g >> 1);
            unsigned wd = (g >> 1) ? pw1 : pw0;
            float4 v = dq4(wd, (g & 1) * 16, ps, pz);
            *(float4*)&sm[boff_dn(buf, kf, bnf, g & 1) + blb] = v;
        }
        __syncthreads();
        if (t + 1 < NT) {
            int k0n = (t + 1) * 32;
            const float4* hp = (const float4*)(hrow + k0n);
            pa[0] = hp[0]; pa[1] = hp[1]; pa[2] = hp[2]; pa[3] = hp[3];
            const int* qp = qr + (k0n >> 3);
            pw0 = (unsigned)qp[0]; pw1 = (unsigned)qp[1];
            int gi = k0n >> 7;
            ps = sr[gi]; pz = (float)zr[gi] * ps;
        }
        #pragma unroll
        for (int kf = 0; kf < 4; kf++) {
            unsigned a[4][4], b[4][2];
            #pragma unroll
            for (int mf = 0; mf < 4; mf++)
                #pragma unroll
                for (int r = 0; r < 4; r++)
                    a[mf][r] = __float_as_uint(sm[aoff(buf, kf, wm * 4 + mf, r) + lane]);
            #pragma unroll
            for (int nf = 0; nf < 4; nf++)
                #pragma unroll
                for (int r = 0; r < 2; r++)
                    b[nf][r] = __float_as_uint(sm[boff_dn(buf, kf, wn * 4 + nf, r) + lane]);
            #pragma unroll
            for (int mf = 0; mf < 4; mf++)
                #pragma unroll
                for (int nf = 0; nf < 4; nf++)
                    mma8(acc[mf][nf], a[mf], b[nf]);
        }
    }

    #pragma unroll
    for (int mf = 0; mf < 4; mf++) {
        #pragma unroll
        for (int hh = 0; hh < 2; hh++) {
            int row = wm * 64 + mf * 16 + (lane >> 2) + hh * 8;
            if (m0 + row < cnt) {
                float wgt = pwv[row];
                float* orow = g_y + (size_t)(off + m0 + row) * H_ + n0;
                #pragma unroll
                for (int nf = 0; nf < 4; nf++) {
                    int col = wn * 32 + nf * 8 + (lane & 3) * 2;
                    float2 v;
                    v.x = wgt * acc[mf][nf][hh * 2];
                    v.y = wgt * acc[mf][nf][hh * 2 + 1];
                    *(float2*)(orow + col) = v;
                }
            }
        }
    }
}

// ================= shared gate/up =================
// block 128 x 64 like expert_gu, B from transposed dense weights
__global__ __launch_bounds__(256, 1) void shared_gu_mma(const float* __restrict__ x)
{
    extern __shared__ float sm[];
    int m0 = blockIdx.y * 128;
    int n0 = blockIdx.x * 64;
    int tid = threadIdx.x;

    int fm = tid & 127, kh = tid >> 7;
    const float* xrow = x + (size_t)(m0 + fm) * H_ + kh * 16;
    int sel = tid >> 7;
    int t2 = tid & 127;
    int fn = t2 & 63, bkh = t2 >> 6;
    const float* brow = (sel ? g_suwT : g_sgwT) + (size_t)(n0 + fn) * H_ + bkh * 16;

    int w = tid >> 5, lane = tid & 31;
    int wm = w & 3, wn = w >> 2;

    float accG[2][4][4] = {};
    float accU[2][4][4] = {};

    float4 pa[4], pb[4];
    {
        const float4* xp = (const float4*)xrow;
        pa[0] = xp[0]; pa[1] = xp[1]; pa[2] = xp[2]; pa[3] = xp[3];
        const float4* bp = (const float4*)brow;
        pb[0] = bp[0]; pb[1] = bp[1]; pb[2] = bp[2]; pb[3] = bp[3];
    }

    const int NT = H_ / 32;
    int amf = fm >> 4, ami8 = (fm & 15) >> 3, alb = (fm & 7) * 4;
    int bnf = fn >> 3, blb = (fn & 7) * 4;

    for (int t = 0; t < NT; t++) {
        int buf = t & 1;
        #pragma unroll
        for (int g = 0; g < 4; g++) {
            int kf = kh * 2 + (g >> 1);
            int p = ami8 + 2 * (g & 1);
            *(float4*)&sm[aoff(buf, kf, amf, p) + alb] = cvt4(pa[g]);
        }
        #pragma unroll
        for (int g = 0; g < 4; g++) {
            int kf = bkh * 2 + (g >> 1);
            *(float4*)&sm[boff_gu(buf, kf, bnf, g & 1, sel) + blb] = pb[g];  // pre-tf32
        }
        __syncthreads();
        if (t + 1 < NT) {
            int k0n = (t + 1) * 32;
            const float4* xp = (const float4*)(xrow + k0n);
            pa[0] = xp[0]; pa[1] = xp[1]; pa[2] = xp[2]; pa[3] = xp[3];
            const float4* bp = (const float4*)(brow + k0n);
            pb[0] = bp[0]; pb[1] = bp[1]; pb[2] = bp[2]; pb[3] = bp[3];
        }
        #pragma unroll
        for (int kf = 0; kf < 4; kf++) {
            unsigned a[2][4], bg[4][2], bu[4][2];
            #pragma unroll
            for (int mf = 0; mf < 2; mf++)
                #pragma unroll
                for (int r = 0; r < 4; r++)
                    a[mf][r] = __float_as_uint(sm[aoff(buf, kf, wm * 2 + mf, r) + lane]);
            #pragma unroll
            for (int nf = 0; nf < 4; nf++)
                #pragma unroll
                for (int r = 0; r < 2; r++) {
                    bg[nf][r] = __float_as_uint(sm[boff_gu(buf, kf, wn * 4 + nf, r, 0) + lane]);
                    bu[nf][r] = __float_as_uint(sm[boff_gu(buf, kf, wn * 4 + nf, r, 1) + lane]);
                }
            #pragma unroll
            for (int mf = 0; mf < 2; mf++)
                #pragma unroll
                for (int nf = 0; nf < 4; nf++) {
                    mma8(accG[mf][nf], a[mf], bg[nf]);
                    mma8(accU[mf][nf], a[mf], bu[nf]);
                }
        }
    }

    #pragma unroll
    for (int mf = 0; mf < 2; mf++) {
        #pragma unroll
        for (int hh = 0; hh < 2; hh++) {
            int row = wm * 32 + mf * 16 + (lane >> 2) + hh * 8;
            float* orow = g_sh + (size_t)(m0 + row) * ISH_ + n0;
            #pragma unroll
            for (int nf = 0; nf < 4; nf++) {
                int col = wn * 32 + nf * 8 + (lane & 3) * 2;
                float2 v;
                v.x = to_tf32(silu_mul(accG[mf][nf][hh * 2],     accU[mf][nf][hh * 2]));
                v.y = to_tf32(silu_mul(accG[mf][nf][hh * 2 + 1], accU[mf][nf][hh * 2 + 1]));
                *(float2*)(orow + col) = v;
            }
        }
    }
}

// ================= shared down + final combine =================
// block 128 x 128 like expert_down
__global__ __launch_bounds__(256, 1) void shared_down_mma(float* __restrict__ out)
{
    extern __shared__ float sm[];
    int m0 = blockIdx.y * 128;
    int n0 = blockIdx.x * 128;
    int tid = threadIdx.x;

    int fm = tid & 127, kh = tid >> 7;
    const float* arow = g_sh + (size_t)(m0 + fm) * ISH_ + kh * 16;
    int fn = tid & 127, bkh = tid >> 7;
    const float* brow = g_sdwT + (size_t)(n0 + fn) * ISH_ + bkh * 16;

    int w = tid >> 5, lane = tid & 31;
    int wm = w & 1, wn = w >> 1;

    float acc[4][4][4] = {};

    float4 pa[4], pb[4];
    {
        const float4* ap = (const float4*)arow;
        pa[0] = ap[0]; pa[1] = ap[1]; pa[2] = ap[2]; pa[3] = ap[3];
        const float4* bp = (const float4*)brow;
        pb[0] = bp[0]; pb[1] = bp[1]; pb[2] = bp[2]; pb[3] = bp[3];
    }

    const int NT = ISH_ / 32;  // 88
    int amf = fm >> 4, ami8 = (fm & 15) >> 3, alb = (fm & 7) * 4;
    int bnf = fn >> 3, blb = (fn & 7) * 4;

    for (int t = 0; t < NT; t++) {
        int buf = t & 1;
        #pragma unroll
        for (int g = 0; g < 4; g++) {
            int kf = kh * 2 + (g >> 1);
            int p = ami8 + 2 * (g & 1);
            *(float4*)&sm[aoff(buf, kf, amf, p) + alb] = pa[g];
        }
        #pragma unroll
        for (int g = 0; g < 4; g++) {
            int kf = bkh * 2 + (g >> 1);
            *(float4*)&sm[boff_dn(buf, kf, bnf, g & 1) + blb] = pb[g];
        }
        __syncthreads();
        if (t + 1 < NT) {
            int k0n = (t + 1) * 32;
            const float4* ap = (const float4*)(arow + k0n);
            pa[0] = ap[0]; pa[1] = ap[1]; pa[2] = ap[2]; pa[3] = ap[3];
            const float4* bp = (const float4*)(brow + k0n);
            pb[0] = bp[0]; pb[1] = bp[1]; pb[2] = bp[2]; pb[3] = bp[3];
        }
        #pragma unroll
        for (int kf = 0; kf < 4; kf++) {
            unsigned a[4][4], b[4][2];
            #pragma unroll
            for (int mf = 0; mf < 4; mf++)
                #pragma unroll
                for (int r = 0; r < 4; r++)
                    a[mf][r] = __float_as_uint(sm[aoff(buf, kf, wm * 4 + mf, r) + lane]);
            #pragma unroll
            for (int nf = 0; nf < 4; nf++)
                #pragma unroll
                for (int r = 0; r < 2; r++)
                    b[nf][r] = __float_as_uint(sm[boff_dn(buf, kf, wn * 4 + nf, r) + lane]);
            #pragma unroll
            for (int mf = 0; mf < 4; mf++)
                #pragma unroll
                for (int nf = 0; nf < 4; nf++)
                    mma8(acc[mf][nf], a[mf], b[nf]);
        }
    }

    // combine shared + 4 routed pair outputs
    #pragma unroll
    for (int mf = 0; mf < 4; mf++) {
        #pragma unroll
        for (int hh = 0; hh < 2; hh++) {
            int row = wm * 64 + mf * 16 + (lane >> 2) + hh * 8;
            int tk = m0 + row;
            int p0 = g_pair_pos[tk][0], p1 = g_pair_pos[tk][1];
            int p2 = g_pair_pos[tk][2], p3 = g_pair_pos[tk][3];
            float* orow = out + (size_t)tk * H_ + n0;
            #pragma unroll
            for (int nf = 0; nf < 4; nf++) {
                int col = wn * 32 + nf * 8 + (lane & 3) * 2;
                float2 y0 = *(const float2*)(g_y + (size_t)p0 * H_ + n0 + col);
                float2 y1 = *(const float2*)(g_y + (size_t)p1 * H_ + n0 + col);
                float2 y2 = *(const float2*)(g_y + (size_t)p2 * H_ + n0 + col);
                float2 y3 = *(const float2*)(g_y + (size_t)p3 * H_ + n0 + col);
                float2 v;
                v.x = acc[mf][nf][hh * 2]     + y0.x + y1.x + y2.x + y3.x;
                v.y = acc[mf][nf][hh * 2 + 1] + y0.y + y1.y + y2.y + y3.y;
                *(float2*)(orow + col) = v;
            }
        }
    }
}

// ---------------- launch ----------------
extern "C" void kernel_launch(void* const* d_in, const int* in_sizes, int n_in,
                              void* d_out, int out_size)
{
    const float* x   = (const float*)d_in[0];
    const float* gw  = (const float*)d_in[1];
    const int*   gq  = (const int*)  d_in[2];
    const int*   gz  = (const int*)  d_in[3];
    const float* gs  = (const float*)d_in[4];
    const int*   uq  = (const int*)  d_in[5];
    const int*   uz  = (const int*)  d_in[6];
    const float* us  = (const float*)d_in[7];
    const int*   dq  = (const int*)  d_in[8];
    const int*   dz  = (const int*)  d_in[9];
    const float* ds  = (const float*)d_in[10];
    const float* sgw = (const float*)d_in[11];
    const float* suw = (const float*)d_in[12];
    const float* sdw = (const float*)d_in[13];
    float* out = (float*)d_out;

    static bool attr_done = false;
    if (!attr_done) {
        cudaFuncSetAttribute(expert_gu_mma,    cudaFuncAttributeMaxDynamicSharedMemorySize, SMEM_BYTES);
        cudaFuncSetAttribute(expert_down_mma,  cudaFuncAttributeMaxDynamicSharedMemorySize, SMEM_BYTES);
        cudaFuncSetAttribute(shared_gu_mma,    cudaFuncAttributeMaxDynamicSharedMemorySize, SMEM_BYTES);
        cudaFuncSetAttribute(shared_down_mma,  cudaFuncAttributeMaxDynamicSharedMemorySize, SMEM_BYTES);
        attr_done = true;
    }

    zero_kernel<<<1, 32>>>();
    router_kernel<<<T_, 256>>>(x, gw);
    scan_kernel<<<1, 32>>>();
    scatter_kernel<<<(T_ + 255) / 256, 256>>>();

    float* sgwT; cudaGetSymbolAddress((void**)&sgwT, g_sgwT);
    float* suwT; cudaGetSymbolAddress((void**)&suwT, g_suwT);
    float* sdwT; cudaGetSymbolAddress((void**)&sdwT, g_sdwT);
    transpose_kernel<<<dim3(ISH_ / 32, H_ / 32), dim3(32, 8)>>>(sgw, sgwT, H_, ISH_);
    transpose_kernel<<<dim3(ISH_ / 32, H_ / 32), dim3(32, 8)>>>(suw, suwT, H_, ISH_);
    transpose_kernel<<<dim3(H_ / 32, ISH_ / 32), dim3(32, 8)>>>(sdw, sdwT, ISH_, H_);

    dim3 ggu(I_ / 64, T_ / 128, E_);       // (22, 8, 32)
    expert_gu_mma<<<ggu, 256, SMEM_BYTES>>>(x, gq, gz, gs, uq, uz, us);

    dim3 gdn(H_ / 128, T_ / 128, E_);      // (16, 8, 32)
    expert_down_mma<<<gdn, 256, SMEM_BYTES>>>(dq, dz, ds);

    dim3 gsg(ISH_ / 64, T_ / 128);         // (44, 8)
    shared_gu_mma<<<gsg, 256, SMEM_BYTES>>>(x);

    dim3 gsd(H_ / 128, T_ / 128);          // (16, 8)
    shared_down_mma<<<gsd, 256, SMEM_BYTES>>>(out);
}

// round 5
// speedup vs baseline: 3.1528x; 1.6290x over previous
#include <cuda_runtime.h>
#include <cuda_fp16.h>
#include <math.h>
#include <stdint.h>

#define E_    32
#define TOPK  4
#define H_    2048
#define I_    1408
#define GS_   128
#define T_    1024
#define ISH_  2816
#define NPAIR (T_*TOPK)

// ---------------- device scratch ----------------
__device__ int    g_counts[E_];
__device__ int    g_offsets[E_];
__device__ int    g_cursor[E_];
__device__ int    g_topk_idx[T_][TOPK];
__device__ float  g_topk_w[T_][TOPK];
__device__ int    g_pair_token[NPAIR];
__device__ float  g_pair_w[NPAIR];
__device__ int    g_pair_pos[T_][TOPK];
__device__ __half g_h[(size_t)NPAIR * I_];
__device__ float  g_y[(size_t)NPAIR * H_];
__device__ __half g_sh[(size_t)T_ * ISH_];
__device__ __half g_sgwT[(size_t)ISH_ * H_];   // [ISH][H]
__device__ __half g_suwT[(size_t)ISH_ * H_];   // [ISH][H]
__device__ __half g_sdwT[(size_t)H_ * ISH_];   // [H][ISH]

// ---------------- helpers ----------------
__device__ __forceinline__ uint32_t f2h2(float a, float b) {
    __half2 h;
    h.x = __float2half_rn(a);
    h.y = __float2half_rn(b);
    return *(uint32_t*)&h;
}
__device__ __forceinline__ uint32_t dqh2(unsigned w, int sh, float s, float zs) {
    float v0 = fmaf((float)((w >> sh) & 15), s, -zs);
    float v1 = fmaf((float)((w >> (sh + 4)) & 15), s, -zs);
    return f2h2(v0, v1);
}
// m16n8k16 f16 mma, fp32 accum
__device__ __forceinline__ void mma16(float* d, const uint32_t* a, const uint32_t* b) {
    asm volatile("mma.sync.aligned.m16n8k16.row.col.f32.f16.f16.f32 "
        "{%0,%1,%2,%3},{%4,%5,%6,%7},{%8,%9},{%0,%1,%2,%3};\n"
        : "+f"(d[0]), "+f"(d[1]), "+f"(d[2]), "+f"(d[3])
        : "r"(a[0]), "r"(a[1]), "r"(a[2]), "r"(a[3]), "r"(b[0]), "r"(b[1]));
}
__device__ __forceinline__ float silu_mul(float g, float u) {
    return g / (1.f + __expf(-g)) * u;
}

// smem word (b32/half2) layout per buffer (4096 words = 16KB):
//  A 128x32: [kf2][mf8][plane4][lane32] = 2048 words
//  B: gu: 2 sel x [kf2][nf8][r2][lane32] = 2048 ; dn: [kf2][nf16][r2][lane32] = 2048
__device__ __forceinline__ int aoffw(int buf, int kf, int mf, int p) {
    return buf * 4096 + ((kf * 8 + mf) * 4 + p) * 32;
}
__device__ __forceinline__ int boffw_gu(int buf, int kf, int nf, int r, int sel) {
    return buf * 4096 + 2048 + sel * 1024 + ((kf * 8 + nf) * 2 + r) * 32;
}
__device__ __forceinline__ int boffw_dn(int buf, int kf, int nf, int r) {
    return buf * 4096 + 2048 + ((kf * 16 + nf) * 2 + r) * 32;
}
#define AUXW 8192
#define SMEM_BYTES ((8192 + 128) * 4)

// ---------------- small kernels ----------------
__global__ void zero_kernel() {
    int i = threadIdx.x;
    if (i < E_) g_counts[i] = 0;
}

__global__ void router_kernel(const float* __restrict__ x, const float* __restrict__ gw) {
    __shared__ float xs[H_];
    __shared__ float part[8][E_];
    __shared__ float scores[E_];
    int t = blockIdx.x;
    for (int h = threadIdx.x; h < H_; h += 256) xs[h] = x[t * H_ + h];
    __syncthreads();
    int e = threadIdx.x & 31;
    int hh = threadIdx.x >> 5;
    float acc = 0.f;
    for (int h = hh; h < H_; h += 8) acc += xs[h] * gw[h * E_ + e];
    part[hh][e] = acc;
    __syncthreads();
    if (threadIdx.x < E_) {
        float s = 0.f;
        #pragma unroll
        for (int i = 0; i < 8; i++) s += part[i][threadIdx.x];
        scores[threadIdx.x] = 1.f / (1.f + expf(-s));
    }
    __syncthreads();
    if (threadIdx.x == 0) {
        bool used[E_];
        #pragma unroll
        for (int i = 0; i < E_; i++) used[i] = false;
        float v[TOPK]; int id[TOPK];
        float sum = 0.f;
        for (int j = 0; j < TOPK; j++) {
            float best = -1e30f; int bi = 0;
            for (int ee = 0; ee < E_; ee++)
                if (!used[ee] && scores[ee] > best) { best = scores[ee]; bi = ee; }
            used[bi] = true; v[j] = best; id[j] = bi; sum += best;
        }
        float inv = 2.5f / (sum + 1e-20f);
        for (int j = 0; j < TOPK; j++) {
            g_topk_idx[t][j] = id[j];
            g_topk_w[t][j] = v[j] * inv;
            atomicAdd(&g_counts[id[j]], 1);
        }
    }
}

__global__ void scan_kernel() {
    if (threadIdx.x == 0) {
        int off = 0;
        for (int e = 0; e < E_; e++) {
            g_offsets[e] = off; g_cursor[e] = off; off += g_counts[e];
        }
    }
}

__global__ void scatter_kernel() {
    int t = blockIdx.x * blockDim.x + threadIdx.x;
    if (t >= T_) return;
    for (int j = 0; j < TOPK; j++) {
        int e = g_topk_idx[t][j];
        int pos = atomicAdd(&g_cursor[e], 1);
        g_pair_token[pos] = t;
        g_pair_w[pos] = g_topk_w[t][j];
        g_pair_pos[t][j] = pos;
    }
}

// in[R][C] fp32 -> out[C][R] half
__global__ void transpose_half(const float* __restrict__ in, __half* __restrict__ out, int R, int C) {
    __shared__ float tile[32][33];
    int c0 = blockIdx.x * 32, r0 = blockIdx.y * 32;
    for (int i = threadIdx.y; i < 32; i += 8)
        tile[i][threadIdx.x] = in[(size_t)(r0 + i) * C + c0 + threadIdx.x];
    __syncthreads();
    for (int i = threadIdx.y; i < 32; i += 8)
        out[(size_t)(c0 + i) * R + r0 + threadIdx.x] = __float2half_rn(tile[threadIdx.x][i]);
}

// ================= expert gate/up: h = silu(X Wg^T) * (X Wu^T) =================
// block 128(M) x 64(N), BK=32, 256 threads, warp tile 32x32 (4 M x 2 N warps)
__global__ __launch_bounds__(256, 2) void expert_gu_mma(
    const float* __restrict__ x,
    const int* __restrict__ gq, const int* __restrict__ gz, const float* __restrict__ gs,
    const int* __restrict__ uq, const int* __restrict__ uz, const float* __restrict__ us)
{
    extern __shared__ uint32_t smw[];
    int e = blockIdx.z;
    int cnt = g_counts[e];
    int m0 = blockIdx.y * 128;
    if (m0 >= cnt) return;
    int off = g_offsets[e];
    int n0 = blockIdx.x * 64;
    int tid = threadIdx.x;

    int* toks = (int*)&smw[AUXW];
    if (tid < 128) {
        int m = m0 + tid;
        toks[tid] = (m < cnt) ? g_pair_token[off + m] : 0;
    }
    __syncthreads();

    // A fill role
    int fm = tid & 127, kh = tid >> 7;
    const float* xrow = x + (size_t)toks[fm] * H_ + kh * 16;
    int amf = fm >> 4, afr = fm & 15;
    int ar0 = (afr & 8) ? 1 : 0, albA = 4 * (afr & 7);
    // B fill role
    int sel = tid >> 7;
    int t2 = tid & 127;
    int fn = t2 & 63, bkh = t2 >> 6;
    long rowb = (long)e * I_ + n0 + fn;
    const int*   qr = (sel ? uq : gq) + rowb * (H_ / 8) + bkh * 2;
    const int*   zr = (sel ? uz : gz) + rowb * (H_ / GS_);
    const float* sr = (sel ? us : gs) + rowb * (H_ / GS_);
    int bnf = fn >> 3, blbB = 4 * (fn & 7);

    int w = tid >> 5, lane = tid & 31;
    int wm = w & 3, wn = w >> 2;

    float accG[2][4][4] = {};
    float accU[2][4][4] = {};

    float4 pa[4]; unsigned pw0, pw1; float ps, pz;
    {
        const float4* xp = (const float4*)xrow;
        pa[0] = xp[0]; pa[1] = xp[1]; pa[2] = xp[2]; pa[3] = xp[3];
        pw0 = (unsigned)qr[0]; pw1 = (unsigned)qr[1];
        ps = sr[0]; pz = (float)zr[0] * ps;
    }

    const int NT = H_ / 32;
    for (int t = 0; t < NT; t++) {
        int buf = t & 1;
        // A store: 2x STS.128
        {
            uint4 u0, u1;
            u0.x = f2h2(pa[0].x, pa[0].y); u0.y = f2h2(pa[0].z, pa[0].w);
            u0.z = f2h2(pa[1].x, pa[1].y); u0.w = f2h2(pa[1].z, pa[1].w);
            u1.x = f2h2(pa[2].x, pa[2].y); u1.y = f2h2(pa[2].z, pa[2].w);
            u1.z = f2h2(pa[3].x, pa[3].y); u1.w = f2h2(pa[3].z, pa[3].w);
            *(uint4*)&smw[aoffw(buf, kh, amf, ar0) + albA] = u0;
            *(uint4*)&smw[aoffw(buf, kh, amf, ar0 + 2) + albA] = u1;
        }
        // B store (dequant): 2x STS.128
        {
            uint4 b0, b1;
            b0.x = dqh2(pw0, 0, ps, pz);  b0.y = dqh2(pw0, 8, ps, pz);
            b0.z = dqh2(pw0, 16, ps, pz); b0.w = dqh2(pw0, 24, ps, pz);
            b1.x = dqh2(pw1, 0, ps, pz);  b1.y = dqh2(pw1, 8, ps, pz);
            b1.z = dqh2(pw1, 16, ps, pz); b1.w = dqh2(pw1, 24, ps, pz);
            *(uint4*)&smw[boffw_gu(buf, bkh, bnf, 0, sel) + blbB] = b0;
            *(uint4*)&smw[boffw_gu(buf, bkh, bnf, 1, sel) + blbB] = b1;
        }
        __syncthreads();
        if (t + 1 < NT) {
            int k0n = (t + 1) * 32;
            const float4* xp = (const float4*)(xrow + k0n);
            pa[0] = xp[0]; pa[1] = xp[1]; pa[2] = xp[2]; pa[3] = xp[3];
            const int* qp = qr + (k0n >> 3);
            pw0 = (unsigned)qp[0]; pw1 = (unsigned)qp[1];
            int gi = k0n >> 7;
            ps = sr[gi]; pz = (float)zr[gi] * ps;
        }
        #pragma unroll
        for (int kf = 0; kf < 2; kf++) {
            uint32_t a[2][4], bg[4][2], bu[4][2];
            #pragma unroll
            for (int mf = 0; mf < 2; mf++)
                #pragma unroll
                for (int r = 0; r < 4; r++)
                    a[mf][r] = smw[aoffw(buf, kf, wm * 2 + mf, r) + lane];
            #pragma unroll
            for (int nf = 0; nf < 4; nf++)
                #pragma unroll
                for (int r = 0; r < 2; r++) {
                    bg[nf][r] = smw[boffw_gu(buf, kf, wn * 4 + nf, r, 0) + lane];
                    bu[nf][r] = smw[boffw_gu(buf, kf, wn * 4 + nf, r, 1) + lane];
                }
            #pragma unroll
            for (int mf = 0; mf < 2; mf++)
                #pragma unroll
                for (int nf = 0; nf < 4; nf++) {
                    mma16(accG[mf][nf], a[mf], bg[nf]);
                    mma16(accU[mf][nf], a[mf], bu[nf]);
                }
        }
    }

    #pragma unroll
    for (int mf = 0; mf < 2; mf++) {
        #pragma unroll
        for (int hh = 0; hh < 2; hh++) {
            int row = wm * 32 + mf * 16 + (lane >> 2) + hh * 8;
            if (m0 + row < cnt) {
                __half* orow = g_h + (size_t)(off + m0 + row) * I_ + n0;
                #pragma unroll
                for (int nf = 0; nf < 4; nf++) {
                    int col = wn * 32 + nf * 8 + (lane & 3) * 2;
                    float vx = silu_mul(accG[mf][nf][hh * 2],     accU[mf][nf][hh * 2]);
                    float vy = silu_mul(accG[mf][nf][hh * 2 + 1], accU[mf][nf][hh * 2 + 1]);
                    uint32_t pk = f2h2(vx, vy);
                    *(uint32_t*)(orow + col) = pk;
                }
            }
        }
    }
}

// ================= expert down: y = pw * (h @ Wd^T) =================
// block 128(M) x 128(N), warp tile 64x32 (2 M x 4 N)
__global__ __launch_bounds__(256, 2) void expert_down_mma(
    const int* __restrict__ dq, const int* __restrict__ dz, const float* __restrict__ ds)
{
    extern __shared__ uint32_t smw[];
    int e = blockIdx.z;
    int cnt = g_counts[e];
    int m0 = blockIdx.y * 128;
    if (m0 >= cnt) return;
    int off = g_offsets[e];
    int n0 = blockIdx.x * 128;
    int tid = threadIdx.x;

    float* pwv = (float*)&smw[AUXW];
    if (tid < 128) {
        int m = m0 + tid;
        pwv[tid] = (m < cnt) ? g_pair_w[off + m] : 0.f;
    }
    __syncthreads();

    int fm = tid & 127, kh = tid >> 7;
    size_t ar = (size_t)off + ((m0 + fm < cnt) ? (m0 + fm) : 0);
    const __half* hrow = g_h + ar * I_ + kh * 16;
    int amf = fm >> 4, afr = fm & 15;
    int ar0 = (afr & 8) ? 1 : 0, albA = 4 * (afr & 7);

    int fn = tid & 127, bkh = tid >> 7;
    long rowb = (long)e * H_ + n0 + fn;
    const int*   qr = dq + rowb * (I_ / 8) + bkh * 2;
    const int*   zr = dz + rowb * (I_ / GS_);
    const float* sr = ds + rowb * (I_ / GS_);
    int bnf = fn >> 3, blbB = 4 * (fn & 7);

    int w = tid >> 5, lane = tid & 31;
    int wm = w & 1, wn = w >> 1;

    float acc[4][4][4] = {};

    uint4 pa0, pa1; unsigned pw0, pw1; float ps, pz;
    {
        const uint4* hp = (const uint4*)hrow;
        pa0 = hp[0]; pa1 = hp[1];
        pw0 = (unsigned)qr[0]; pw1 = (unsigned)qr[1];
        ps = sr[0]; pz = (float)zr[0] * ps;
    }

    const int NT = I_ / 32;  // 44
    for (int t = 0; t < NT; t++) {
        int buf = t & 1;
        *(uint4*)&smw[aoffw(buf, kh, amf, ar0) + albA] = pa0;
        *(uint4*)&smw[aoffw(buf, kh, amf, ar0 + 2) + albA] = pa1;
        {
            uint4 b0, b1;
            b0.x = dqh2(pw0, 0, ps, pz);  b0.y = dqh2(pw0, 8, ps, pz);
            b0.z = dqh2(pw0, 16, ps, pz); b0.w = dqh2(pw0, 24, ps, pz);
            b1.x = dqh2(pw1, 0, ps, pz);  b1.y = dqh2(pw1, 8, ps, pz);
            b1.z = dqh2(pw1, 16, ps, pz); b1.w = dqh2(pw1, 24, ps, pz);
            *(uint4*)&smw[boffw_dn(buf, bkh, bnf, 0) + blbB] = b0;
            *(uint4*)&smw[boffw_dn(buf, bkh, bnf, 1) + blbB] = b1;
        }
        __syncthreads();
        if (t + 1 < NT) {
            int k0n = (t + 1) * 32;
            const uint4* hp = (const uint4*)(hrow + k0n);
            pa0 = hp[0]; pa1 = hp[1];
            const int* qp = qr + (k0n >> 3);
            pw0 = (unsigned)qp[0]; pw1 = (unsigned)qp[1];
            int gi = k0n >> 7;
            ps = sr[gi]; pz = (float)zr[gi] * ps;
        }
        #pragma unroll
        for (int kf = 0; kf < 2; kf++) {
            uint32_t a[4][4], b[4][2];
            #pragma unroll
            for (int mf = 0; mf < 4; mf++)
                #pragma unroll
                for (int r = 0; r < 4; r++)
                    a[mf][r] = smw[aoffw(buf, kf, wm * 4 + mf, r) + lane];
            #pragma unroll
            for (int nf = 0; nf < 4; nf++)
                #pragma unroll
                for (int r = 0; r < 2; r++)
                    b[nf][r] = smw[boffw_dn(buf, kf, wn * 4 + nf, r) + lane];
            #pragma unroll
            for (int mf = 0; mf < 4; mf++)
                #pragma unroll
                for (int nf = 0; nf < 4; nf++)
                    mma16(acc[mf][nf], a[mf], b[nf]);
        }
    }

    #pragma unroll
    for (int mf = 0; mf < 4; mf++) {
        #pragma unroll
        for (int hh = 0; hh < 2; hh++) {
            int row = wm * 64 + mf * 16 + (lane >> 2) + hh * 8;
            if (m0 + row < cnt) {
                float wgt = pwv[row];
                float* orow = g_y + (size_t)(off + m0 + row) * H_ + n0;
                #pragma unroll
                for (int nf = 0; nf < 4; nf++) {
                    int col = wn * 32 + nf * 8 + (lane & 3) * 2;
                    float2 v;
                    v.x = wgt * acc[mf][nf][hh * 2];
                    v.y = wgt * acc[mf][nf][hh * 2 + 1];
                    *(float2*)(orow + col) = v;
                }
            }
        }
    }
}

// ================= shared gate/up =================
__global__ __launch_bounds__(256, 2) void shared_gu_mma(const float* __restrict__ x)
{
    extern __shared__ uint32_t smw[];
    int m0 = blockIdx.y * 128;
    int n0 = blockIdx.x * 64;
    int tid = threadIdx.x;

    int fm = tid & 127, kh = tid >> 7;
    const float* xrow = x + (size_t)(m0 + fm) * H_ + kh * 16;
    int amf = fm >> 4, afr = fm & 15;
    int ar0 = (afr & 8) ? 1 : 0, albA = 4 * (afr & 7);

    int sel = tid >> 7;
    int t2 = tid & 127;
    int fn = t2 & 63, bkh = t2 >> 6;
    const __half* brow = (sel ? g_suwT : g_sgwT) + (size_t)(n0 + fn) * H_ + bkh * 16;
    int bnf = fn >> 3, blbB = 4 * (fn & 7);

    int w = tid >> 5, lane = tid & 31;
    int wm = w & 3, wn = w >> 2;

    float accG[2][4][4] = {};
    float accU[2][4][4] = {};

    float4 pa[4]; uint4 pb0, pb1;
    {
        const float4* xp = (const float4*)xrow;
        pa[0] = xp[0]; pa[1] = xp[1]; pa[2] = xp[2]; pa[3] = xp[3];
        const uint4* bp = (const uint4*)brow;
        pb0 = bp[0]; pb1 = bp[1];
    }

    const int NT = H_ / 32;
    for (int t = 0; t < NT; t++) {
        int buf = t & 1;
        {
            uint4 u0, u1;
            u0.x = f2h2(pa[0].x, pa[0].y); u0.y = f2h2(pa[0].z, pa[0].w);
            u0.z = f2h2(pa[1].x, pa[1].y); u0.w = f2h2(pa[1].z, pa[1].w);
            u1.x = f2h2(pa[2].x, pa[2].y); u1.y = f2h2(pa[2].z, pa[2].w);
            u1.z = f2h2(pa[3].x, pa[3].y); u1.w = f2h2(pa[3].z, pa[3].w);
            *(uint4*)&smw[aoffw(buf, kh, amf, ar0) + albA] = u0;
            *(uint4*)&smw[aoffw(buf, kh, amf, ar0 + 2) + albA] = u1;
        }
        *(uint4*)&smw[boffw_gu(buf, bkh, bnf, 0, sel) + blbB] = pb0;
        *(uint4*)&smw[boffw_gu(buf, bkh, bnf, 1, sel) + blbB] = pb1;
        __syncthreads();
        if (t + 1 < NT) {
            int k0n = (t + 1) * 32;
            const float4* xp = (const float4*)(xrow + k0n);
            pa[0] = xp[0]; pa[1] = xp[1]; pa[2] = xp[2]; pa[3] = xp[3];
            const uint4* bp = (const uint4*)(brow + k0n);
            pb0 = bp[0]; pb1 = bp[1];
        }
        #pragma unroll
        for (int kf = 0; kf < 2; kf++) {
            uint32_t a[2][4], bg[4][2], bu[4][2];
            #pragma unroll
            for (int mf = 0; mf < 2; mf++)
                #pragma unroll
                for (int r = 0; r < 4; r++)
                    a[mf][r] = smw[aoffw(buf, kf, wm * 2 + mf, r) + lane];
            #pragma unroll
            for (int nf = 0; nf < 4; nf++)
                #pragma unroll
                for (int r = 0; r < 2; r++) {
                    bg[nf][r] = smw[boffw_gu(buf, kf, wn * 4 + nf, r, 0) + lane];
                    bu[nf][r] = smw[boffw_gu(buf, kf, wn * 4 + nf, r, 1) + lane];
                }
            #pragma unroll
            for (int mf = 0; mf < 2; mf++)
                #pragma unroll
                for (int nf = 0; nf < 4; nf++) {
                    mma16(accG[mf][nf], a[mf], bg[nf]);
                    mma16(accU[mf][nf], a[mf], bu[nf]);
                }
        }
    }

    #pragma unroll
    for (int mf = 0; mf < 2; mf++) {
        #pragma unroll
        for (int hh = 0; hh < 2; hh++) {
            int row = wm * 32 + mf * 16 + (lane >> 2) + hh * 8;
            __half* orow = g_sh + (size_t)(m0 + row) * ISH_ + n0;
            #pragma unroll
            for (int nf = 0; nf < 4; nf++) {
                int col = wn * 32 + nf * 8 + (lane & 3) * 2;
                float vx = silu_mul(accG[mf][nf][hh * 2],     accU[mf][nf][hh * 2]);
                float vy = silu_mul(accG[mf][nf][hh * 2 + 1], accU[mf][nf][hh * 2 + 1]);
                uint32_t pk = f2h2(vx, vy);
                *(uint32_t*)(orow + col) = pk;
            }
        }
    }
}

// ================= shared down + final combine =================
__global__ __launch_bounds__(256, 2) void shared_down_mma(float* __restrict__ out)
{
    extern __shared__ uint32_t smw[];
    int m0 = blockIdx.y * 128;
    int n0 = blockIdx.x * 128;
    int tid = threadIdx.x;

    int fm = tid & 127, kh = tid >> 7;
    const __half* arow = g_sh + (size_t)(m0 + fm) * ISH_ + kh * 16;
    int amf = fm >> 4, afr = fm & 15;
    int ar0 = (afr & 8) ? 1 : 0, albA = 4 * (afr & 7);

    int fn = tid & 127, bkh = tid >> 7;
    const __half* brow = g_sdwT + (size_t)(n0 + fn) * ISH_ + bkh * 16;
    int bnf = fn >> 3, blbB = 4 * (fn & 7);

    int w = tid >> 5, lane = tid & 31;
    int wm = w & 1, wn = w >> 1;

    float acc[4][4][4] = {};

    uint4 pa0, pa1, pb0, pb1;
    {
        const uint4* ap = (const uint4*)arow;
        pa0 = ap[0]; pa1 = ap[1];
        const uint4* bp = (const uint4*)brow;
        pb0 = bp[0]; pb1 = bp[1];
    }

    const int NT = ISH_ / 32;  // 88
    for (int t = 0; t < NT; t++) {
        int buf = t & 1;
        *(uint4*)&smw[aoffw(buf, kh, amf, ar0) + albA] = pa0;
        *(uint4*)&smw[aoffw(buf, kh, amf, ar0 + 2) + albA] = pa1;
        *(uint4*)&smw[boffw_dn(buf, bkh, bnf, 0) + blbB] = pb0;
        *(uint4*)&smw[boffw_dn(buf, bkh, bnf, 1) + blbB] = pb1;
        __syncthreads();
        if (t + 1 < NT) {
            int k0n = (t + 1) * 32;
            const uint4* ap = (const uint4*)(arow + k0n);
            pa0 = ap[0]; pa1 = ap[1];
            const uint4* bp = (const uint4*)(brow + k0n);
            pb0 = bp[0]; pb1 = bp[1];
        }
        #pragma unroll
        for (int kf = 0; kf < 2; kf++) {
            uint32_t a[4][4], b[4][2];
            #pragma unroll
            for (int mf = 0; mf < 4; mf++)
                #pragma unroll
                for (int r = 0; r < 4; r++)
                    a[mf][r] = smw[aoffw(buf, kf, wm * 4 + mf, r) + lane];
            #pragma unroll
            for (int nf = 0; nf < 4; nf++)
                #pragma unroll
                for (int r = 0; r < 2; r++)
                    b[nf][r] = smw[boffw_dn(buf, kf, wn * 4 + nf, r) + lane];
            #pragma unroll
            for (int mf = 0; mf < 4; mf++)
                #pragma unroll
                for (int nf = 0; nf < 4; nf++)
                    mma16(acc[mf][nf], a[mf], b[nf]);
        }
    }

    #pragma unroll
    for (int mf = 0; mf < 4; mf++) {
        #pragma unroll
        for (int hh = 0; hh < 2; hh++) {
            int row = wm * 64 + mf * 16 + (lane >> 2) + hh * 8;
            int tk = m0 + row;
            int p0 = g_pair_pos[tk][0], p1 = g_pair_pos[tk][1];
            int p2 = g_pair_pos[tk][2], p3 = g_pair_pos[tk][3];
            float* orow = out + (size_t)tk * H_ + n0;
            #pragma unroll
            for (int nf = 0; nf < 4; nf++) {
                int col = wn * 32 + nf * 8 + (lane & 3) * 2;
                float2 y0 = *(const float2*)(g_y + (size_t)p0 * H_ + n0 + col);
                float2 y1 = *(const float2*)(g_y + (size_t)p1 * H_ + n0 + col);
                float2 y2 = *(const float2*)(g_y + (size_t)p2 * H_ + n0 + col);
                float2 y3 = *(const float2*)(g_y + (size_t)p3 * H_ + n0 + col);
                float2 v;
                v.x = acc[mf][nf][hh * 2]     + y0.x + y1.x + y2.x + y3.x;
                v.y = acc[mf][nf][hh * 2 + 1] + y0.y + y1.y + y2.y + y3.y;
                *(float2*)(orow + col) = v;
            }
        }
    }
}

// ---------------- launch ----------------
extern "C" void kernel_launch(void* const* d_in, const int* in_sizes, int n_in,
                              void* d_out, int out_size)
{
    const float* x   = (const float*)d_in[0];
    const float* gw  = (const float*)d_in[1];
    const int*   gq  = (const int*)  d_in[2];
    const int*   gz  = (const int*)  d_in[3];
    const float* gs  = (const float*)d_in[4];
    const int*   uq  = (const int*)  d_in[5];
    const int*   uz  = (const int*)  d_in[6];
    const float* us  = (const float*)d_in[7];
    const int*   dq  = (const int*)  d_in[8];
    const int*   dz  = (const int*)  d_in[9];
    const float* ds  = (const float*)d_in[10];
    const float* sgw = (const float*)d_in[11];
    const float* suw = (const float*)d_in[12];
    const float* sdw = (const float*)d_in[13];
    float* out = (float*)d_out;

    static bool attr_done = false;
    if (!attr_done) {
        cudaFuncSetAttribute(expert_gu_mma,   cudaFuncAttributeMaxDynamicSharedMemorySize, SMEM_BYTES);
        cudaFuncSetAttribute(expert_down_mma, cudaFuncAttributeMaxDynamicSharedMemorySize, SMEM_BYTES);
        cudaFuncSetAttribute(shared_gu_mma,   cudaFuncAttributeMaxDynamicSharedMemorySize, SMEM_BYTES);
        cudaFuncSetAttribute(shared_down_mma, cudaFuncAttributeMaxDynamicSharedMemorySize, SMEM_BYTES);
        attr_done = true;
    }

    zero_kernel<<<1, 32>>>();
    router_kernel<<<T_, 256>>>(x, gw);
    scan_kernel<<<1, 32>>>();
    scatter_kernel<<<(T_ + 255) / 256, 256>>>();

    __half* sgwT; cudaGetSymbolAddress((void**)&sgwT, g_sgwT);
    __half* suwT; cudaGetSymbolAddress((void**)&suwT, g_suwT);
    __half* sdwT; cudaGetSymbolAddress((void**)&sdwT, g_sdwT);
    transpose_half<<<dim3(ISH_ / 32, H_ / 32), dim3(32, 8)>>>(sgw, sgwT, H_, ISH_);
    transpose_half<<<dim3(ISH_ / 32, H_ / 32), dim3(32, 8)>>>(suw, suwT, H_, ISH_);
    transpose_half<<<dim3(H_ / 32, ISH_ / 32), dim3(32, 8)>>>(sdw, sdwT, ISH_, H_);

    dim3 ggu(I_ / 64, T_ / 128, E_);       // (22, 8, 32)
    expert_gu_mma<<<ggu, 256, SMEM_BYTES>>>(x, gq, gz, gs, uq, uz, us);

    dim3 gdn(H_ / 128, T_ / 128, E_);      // (16, 8, 32)
    expert_down_mma<<<gdn, 256, SMEM_BYTES>>>(dq, dz, ds);

    dim3 gsg(ISH_ / 64, T_ / 128);         // (44, 8)
    shared_gu_mma<<<gsg, 256, SMEM_BYTES>>>(x);

    dim3 gsd(H_ / 128, T_ / 128);          // (16, 8)
    shared_down_mma<<<gsd, 256, SMEM_BYTES>>>(out);
}

// round 6
// speedup vs baseline: 3.1815x; 1.0091x over previous
#include <cuda_runtime.h>
#include <cuda_fp16.h>
#include <math.h>
#include <stdint.h>

#define E_    32
#define TOPK  4
#define H_    2048
#define I_    1408
#define GS_   128
#define T_    1024
#define ISH_  2816
#define NPAIR (T_*TOPK)

// ---------------- device scratch ----------------
__device__ int    g_counts[E_];
__device__ int    g_offsets[E_];
__device__ int    g_cursor[E_];
__device__ int    g_topk_idx[T_][TOPK];
__device__ float  g_topk_w[T_][TOPK];
__device__ int    g_pair_token[NPAIR];
__device__ float  g_pair_w[NPAIR];
__device__ int    g_pair_pos[T_][TOPK];
__device__ __half g_h[(size_t)NPAIR * I_];
__device__ float  g_y[(size_t)NPAIR * H_];
__device__ __half g_sh[(size_t)T_ * ISH_];
__device__ __half g_sgwT[(size_t)ISH_ * H_];   // [ISH][H]
__device__ __half g_suwT[(size_t)ISH_ * H_];   // [ISH][H]
__device__ __half g_sdwT[(size_t)H_ * ISH_];   // [H][ISH]

// ---------------- helpers ----------------
__device__ __forceinline__ uint32_t f2h2(float a, float b) {
    __half2 h;
    h.x = __float2half_rn(a);
    h.y = __float2half_rn(b);
    return *(uint32_t*)&h;
}
__device__ __forceinline__ uint32_t dqh2(unsigned w, int sh, float s, float zs) {
    float v0 = fmaf((float)((w >> sh) & 15), s, -zs);
    float v1 = fmaf((float)((w >> (sh + 4)) & 15), s, -zs);
    return f2h2(v0, v1);
}
// dequant one 32-bit word (8 codes) -> uint4 (4 half2)
__device__ __forceinline__ uint4 dqw(unsigned w, float s, float zs) {
    uint4 v;
    v.x = dqh2(w, 0, s, zs);  v.y = dqh2(w, 8, s, zs);
    v.z = dqh2(w, 16, s, zs); v.w = dqh2(w, 24, s, zs);
    return v;
}
// pack 2 float4 -> uint4 of half2
__device__ __forceinline__ uint4 packh(float4 a, float4 b) {
    uint4 u;
    u.x = f2h2(a.x, a.y); u.y = f2h2(a.z, a.w);
    u.z = f2h2(b.x, b.y); u.w = f2h2(b.z, b.w);
    return u;
}
// m16n8k16 f16 mma, fp32 accum
__device__ __forceinline__ void mma16(float* d, const uint32_t* a, const uint32_t* b) {
    asm volatile("mma.sync.aligned.m16n8k16.row.col.f32.f16.f16.f32 "
        "{%0,%1,%2,%3},{%4,%5,%6,%7},{%8,%9},{%0,%1,%2,%3};\n"
        : "+f"(d[0]), "+f"(d[1]), "+f"(d[2]), "+f"(d[3])
        : "r"(a[0]), "r"(a[1]), "r"(a[2]), "r"(a[3]), "r"(b[0]), "r"(b[1]));
}
__device__ __forceinline__ float silu_mul(float g, float u) {
    return g / (1.f + __expf(-g)) * u;
}

// smem word (b32/half2) layout per buffer (8192 words = 32KB), BK=64 (kf 0..3):
//  A 128x64: [kf4][mf8][plane4][lane32] = 4096 words
//  B gu: 2 sel x [kf4][nf8][r2][lane32] = 4096 ; B dn: [kf4][nf16][r2][lane32] = 4096
__device__ __forceinline__ int aoffw(int buf, int kf, int mf, int p) {
    return buf * 8192 + ((kf * 8 + mf) * 4 + p) * 32;
}
__device__ __forceinline__ int boffw_gu(int buf, int kf, int nf, int r, int sel) {
    return buf * 8192 + 4096 + sel * 2048 + ((kf * 8 + nf) * 2 + r) * 32;
}
__device__ __forceinline__ int boffw_dn(int buf, int kf, int nf, int r) {
    return buf * 8192 + 4096 + ((kf * 16 + nf) * 2 + r) * 32;
}
#define AUXW 16384
#define SMEM_BYTES ((16384 + 128) * 4)

// ---------------- small kernels ----------------
__global__ void zero_kernel() {
    int i = threadIdx.x;
    if (i < E_) g_counts[i] = 0;
}

__global__ void router_kernel(const float* __restrict__ x, const float* __restrict__ gw) {
    __shared__ float xs[H_];
    __shared__ float part[8][E_];
    __shared__ float scores[E_];
    int t = blockIdx.x;
    for (int h = threadIdx.x; h < H_; h += 256) xs[h] = x[t * H_ + h];
    __syncthreads();
    int e = threadIdx.x & 31;
    int hh = threadIdx.x >> 5;
    float acc = 0.f;
    for (int h = hh; h < H_; h += 8) acc += xs[h] * gw[h * E_ + e];
    part[hh][e] = acc;
    __syncthreads();
    if (threadIdx.x < E_) {
        float s = 0.f;
        #pragma unroll
        for (int i = 0; i < 8; i++) s += part[i][threadIdx.x];
        scores[threadIdx.x] = 1.f / (1.f + expf(-s));
    }
    __syncthreads();
    if (threadIdx.x == 0) {
        bool used[E_];
        #pragma unroll
        for (int i = 0; i < E_; i++) used[i] = false;
        float v[TOPK]; int id[TOPK];
        float sum = 0.f;
        for (int j = 0; j < TOPK; j++) {
            float best = -1e30f; int bi = 0;
            for (int ee = 0; ee < E_; ee++)
                if (!used[ee] && scores[ee] > best) { best = scores[ee]; bi = ee; }
            used[bi] = true; v[j] = best; id[j] = bi; sum += best;
        }
        float inv = 2.5f / (sum + 1e-20f);
        for (int j = 0; j < TOPK; j++) {
            g_topk_idx[t][j] = id[j];
            g_topk_w[t][j] = v[j] * inv;
            atomicAdd(&g_counts[id[j]], 1);
        }
    }
}

__global__ void scan_kernel() {
    if (threadIdx.x == 0) {
        int off = 0;
        for (int e = 0; e < E_; e++) {
            g_offsets[e] = off; g_cursor[e] = off; off += g_counts[e];
        }
    }
}

__global__ void scatter_kernel() {
    int t = blockIdx.x * blockDim.x + threadIdx.x;
    if (t >= T_) return;
    for (int j = 0; j < TOPK; j++) {
        int e = g_topk_idx[t][j];
        int pos = atomicAdd(&g_cursor[e], 1);
        g_pair_token[pos] = t;
        g_pair_w[pos] = g_topk_w[t][j];
        g_pair_pos[t][j] = pos;
    }
}

// in[R][C] fp32 -> out[C][R] half
__global__ void transpose_half(const float* __restrict__ in, __half* __restrict__ out, int R, int C) {
    __shared__ float tile[32][33];
    int c0 = blockIdx.x * 32, r0 = blockIdx.y * 32;
    for (int i = threadIdx.y; i < 32; i += 8)
        tile[i][threadIdx.x] = in[(size_t)(r0 + i) * C + c0 + threadIdx.x];
    __syncthreads();
    for (int i = threadIdx.y; i < 32; i += 8)
        out[(size_t)(c0 + i) * R + r0 + threadIdx.x] = __float2half_rn(tile[threadIdx.x][i]);
}

// ================= expert gate/up: h = silu(X Wg^T) * (X Wu^T) =================
// block 128(M) x 64(N), BK=64, 256 threads, warp tile 32x32 (4 M x 2 N warps)
__global__ __launch_bounds__(256, 2) void expert_gu_mma(
    const float* __restrict__ x,
    const int* __restrict__ gq, const int* __restrict__ gz, const float* __restrict__ gs,
    const int* __restrict__ uq, const int* __restrict__ uz, const float* __restrict__ us)
{
    extern __shared__ uint32_t smw[];
    int e = blockIdx.z;
    int cnt = g_counts[e];
    int m0 = blockIdx.y * 128;
    if (m0 >= cnt) return;
    int off = g_offsets[e];
    int n0 = blockIdx.x * 64;
    int tid = threadIdx.x;

    int* toks = (int*)&smw[AUXW];
    if (tid < 128) {
        int m = m0 + tid;
        toks[tid] = (m < cnt) ? g_pair_token[off + m] : 0;
    }
    __syncthreads();

    // A fill role: row fm, k-half kh (32 floats)
    int fm = tid & 127, kh = tid >> 7;
    const float4* xrow4 = (const float4*)(x + (size_t)toks[fm] * H_ + kh * 32);
    int amf = fm >> 4, ami8 = (fm & 15) >> 3, albA = 4 * (fm & 7);
    // B fill role: sel, row fn, k-half bkh (32 codes = 1 int4)
    int sel = tid >> 7;
    int t2 = tid & 127;
    int fn = t2 & 63, bkh = t2 >> 6;
    long rowb = (long)e * I_ + n0 + fn;
    const int4*  qr4 = (const int4*)((sel ? uq : gq) + rowb * (H_ / 8));
    const int*   zr  = (sel ? uz : gz) + rowb * (H_ / GS_);
    const float* sr  = (sel ? us : gs) + rowb * (H_ / GS_);
    int bnf = fn >> 3, blbB = 4 * (fn & 7);

    int w = tid >> 5, lane = tid & 31;
    int wm = w & 3, wn = w >> 2;

    float accG[2][4][4] = {};
    float accU[2][4][4] = {};

    float4 pa[8]; int4 pq; float ps, pz;
    {
        #pragma unroll
        for (int i = 0; i < 8; i++) pa[i] = xrow4[i];
        pq = qr4[bkh];
        ps = sr[0]; pz = (float)zr[0] * ps;
    }

    const int NT = H_ / 64;  // 32
    for (int t = 0; t < NT; t++) {
        int buf = t & 1;
        // A store: 4x STS.128  (gg covers k local kh*32 + gg*8)
        #pragma unroll
        for (int gg = 0; gg < 4; gg++) {
            int kf = kh * 2 + (gg >> 1);
            int p = ami8 + 2 * (gg & 1);
            *(uint4*)&smw[aoffw(buf, kf, amf, p) + albA] = packh(pa[gg * 2], pa[gg * 2 + 1]);
        }
        // B store (dequant): 4x STS.128 (word w covers k local bkh*32 + w*8)
        {
            unsigned wd[4] = {(unsigned)pq.x, (unsigned)pq.y, (unsigned)pq.z, (unsigned)pq.w};
            #pragma unroll
            for (int wi = 0; wi < 4; wi++) {
                int kf = bkh * 2 + (wi >> 1);
                int r = wi & 1;
                *(uint4*)&smw[boffw_gu(buf, kf, bnf, r, sel) + blbB] = dqw(wd[wi], ps, pz);
            }
        }
        __syncthreads();
        if (t + 1 < NT) {
            const float4* xp = xrow4 + (t + 1) * 16;
            #pragma unroll
            for (int i = 0; i < 8; i++) pa[i] = xp[i];
            pq = qr4[(t + 1) * 2 + bkh];
            int gi = (t + 1) >> 1;
            ps = sr[gi]; pz = (float)zr[gi] * ps;
        }
        #pragma unroll
        for (int kf = 0; kf < 4; kf++) {
            uint32_t a[2][4], bg[4][2], bu[4][2];
            #pragma unroll
            for (int mf = 0; mf < 2; mf++)
                #pragma unroll
                for (int r = 0; r < 4; r++)
                    a[mf][r] = smw[aoffw(buf, kf, wm * 2 + mf, r) + lane];
            #pragma unroll
            for (int nf = 0; nf < 4; nf++)
                #pragma unroll
                for (int r = 0; r < 2; r++) {
                    bg[nf][r] = smw[boffw_gu(buf, kf, wn * 4 + nf, r, 0) + lane];
                    bu[nf][r] = smw[boffw_gu(buf, kf, wn * 4 + nf, r, 1) + lane];
                }
            #pragma unroll
            for (int mf = 0; mf < 2; mf++)
                #pragma unroll
                for (int nf = 0; nf < 4; nf++) {
                    mma16(accG[mf][nf], a[mf], bg[nf]);
                    mma16(accU[mf][nf], a[mf], bu[nf]);
                }
        }
    }

    #pragma unroll
    for (int mf = 0; mf < 2; mf++) {
        #pragma unroll
        for (int hh = 0; hh < 2; hh++) {
            int row = wm * 32 + mf * 16 + (lane >> 2) + hh * 8;
            if (m0 + row < cnt) {
                __half* orow = g_h + (size_t)(off + m0 + row) * I_ + n0;
                #pragma unroll
                for (int nf = 0; nf < 4; nf++) {
                    int col = wn * 32 + nf * 8 + (lane & 3) * 2;
                    float vx = silu_mul(accG[mf][nf][hh * 2],     accU[mf][nf][hh * 2]);
                    float vy = silu_mul(accG[mf][nf][hh * 2 + 1], accU[mf][nf][hh * 2 + 1]);
                    *(uint32_t*)(orow + col) = f2h2(vx, vy);
                }
            }
        }
    }
}

// ================= expert down: y = pw * (h @ Wd^T) =================
// block 128(M) x 128(N), BK=64, warp tile 64x32 (2 M x 4 N)
__global__ __launch_bounds__(256, 2) void expert_down_mma(
    const int* __restrict__ dq, const int* __restrict__ dz, const float* __restrict__ ds)
{
    extern __shared__ uint32_t smw[];
    int e = blockIdx.z;
    int cnt = g_counts[e];
    int m0 = blockIdx.y * 128;
    if (m0 >= cnt) return;
    int off = g_offsets[e];
    int n0 = blockIdx.x * 128;
    int tid = threadIdx.x;

    float* pwv = (float*)&smw[AUXW];
    if (tid < 128) {
        int m = m0 + tid;
        pwv[tid] = (m < cnt) ? g_pair_w[off + m] : 0.f;
    }
    __syncthreads();

    int fm = tid & 127, kh = tid >> 7;
    size_t ar = (size_t)off + ((m0 + fm < cnt) ? (m0 + fm) : 0);
    const uint4* hrow4 = (const uint4*)(g_h + ar * I_ + kh * 32);
    int amf = fm >> 4, ami8 = (fm & 15) >> 3, albA = 4 * (fm & 7);

    int fn = tid & 127, bkh = tid >> 7;
    long rowb = (long)e * H_ + n0 + fn;
    const int4*  qr4 = (const int4*)(dq + rowb * (I_ / 8));
    const int*   zr  = dz + rowb * (I_ / GS_);
    const float* sr  = ds + rowb * (I_ / GS_);
    int bnf = fn >> 3, blbB = 4 * (fn & 7);

    int w = tid >> 5, lane = tid & 31;
    int wm = w & 1, wn = w >> 1;

    float acc[4][4][4] = {};

    uint4 pa[4]; int4 pq; float ps, pz;
    {
        #pragma unroll
        for (int i = 0; i < 4; i++) pa[i] = hrow4[i];
        pq = qr4[bkh];
        ps = sr[0]; pz = (float)zr[0] * ps;
    }

    const int NT = I_ / 64;  // 22
    for (int t = 0; t < NT; t++) {
        int buf = t & 1;
        #pragma unroll
        for (int g = 0; g < 4; g++) {
            int kf = kh * 2 + (g >> 1);
            int p = ami8 + 2 * (g & 1);
            *(uint4*)&smw[aoffw(buf, kf, amf, p) + albA] = pa[g];
        }
        {
            unsigned wd[4] = {(unsigned)pq.x, (unsigned)pq.y, (unsigned)pq.z, (unsigned)pq.w};
            #pragma unroll
            for (int wi = 0; wi < 4; wi++) {
                int kf = bkh * 2 + (wi >> 1);
                int r = wi & 1;
                *(uint4*)&smw[boffw_dn(buf, kf, bnf, r) + blbB] = dqw(wd[wi], ps, pz);
            }
        }
        __syncthreads();
        if (t + 1 < NT) {
            const uint4* hp = hrow4 + (t + 1) * 8;
            #pragma unroll
            for (int i = 0; i < 4; i++) pa[i] = hp[i];
            pq = qr4[(t + 1) * 2 + bkh];
            int gi = (t + 1) >> 1;
            ps = sr[gi]; pz = (float)zr[gi] * ps;
        }
        #pragma unroll
        for (int kf = 0; kf < 4; kf++) {
            uint32_t a[4][4], b[4][2];
            #pragma unroll
            for (int mf = 0; mf < 4; mf++)
                #pragma unroll
                for (int r = 0; r < 4; r++)
                    a[mf][r] = smw[aoffw(buf, kf, wm * 4 + mf, r) + lane];
            #pragma unroll
            for (int nf = 0; nf < 4; nf++)
                #pragma unroll
                for (int r = 0; r < 2; r++)
                    b[nf][r] = smw[boffw_dn(buf, kf, wn * 4 + nf, r) + lane];
            #pragma unroll
            for (int mf = 0; mf < 4; mf++)
                #pragma unroll
                for (int nf = 0; nf < 4; nf++)
                    mma16(acc[mf][nf], a[mf], b[nf]);
        }
    }

    #pragma unroll
    for (int mf = 0; mf < 4; mf++) {
        #pragma unroll
        for (int hh = 0; hh < 2; hh++) {
            int row = wm * 64 + mf * 16 + (lane >> 2) + hh * 8;
            if (m0 + row < cnt) {
                float wgt = pwv[row];
                float* orow = g_y + (size_t)(off + m0 + row) * H_ + n0;
                #pragma unroll
                for (int nf = 0; nf < 4; nf++) {
                    int col = wn * 32 + nf * 8 + (lane & 3) * 2;
                    float2 v;
                    v.x = wgt * acc[mf][nf][hh * 2];
                    v.y = wgt * acc[mf][nf][hh * 2 + 1];
                    *(float2*)(orow + col) = v;
                }
            }
        }
    }
}

// ================= shared gate/up =================
__global__ __launch_bounds__(256, 2) void shared_gu_mma(const float* __restrict__ x)
{
    extern __shared__ uint32_t smw[];
    int m0 = blockIdx.y * 128;
    int n0 = blockIdx.x * 64;
    int tid = threadIdx.x;

    int fm = tid & 127, kh = tid >> 7;
    const float4* xrow4 = (const float4*)(x + (size_t)(m0 + fm) * H_ + kh * 32);
    int amf = fm >> 4, ami8 = (fm & 15) >> 3, albA = 4 * (fm & 7);

    int sel = tid >> 7;
    int t2 = tid & 127;
    int fn = t2 & 63, bkh = t2 >> 6;
    const uint4* brow4 = (const uint4*)((sel ? g_suwT : g_sgwT) + (size_t)(n0 + fn) * H_ + bkh * 32);
    int bnf = fn >> 3, blbB = 4 * (fn & 7);

    int w = tid >> 5, lane = tid & 31;
    int wm = w & 3, wn = w >> 2;

    float accG[2][4][4] = {};
    float accU[2][4][4] = {};

    float4 pa[8]; uint4 pb[4];
    {
        #pragma unroll
        for (int i = 0; i < 8; i++) pa[i] = xrow4[i];
        #pragma unroll
        for (int i = 0; i < 4; i++) pb[i] = brow4[i];
    }

    const int NT = H_ / 64;  // 32
    for (int t = 0; t < NT; t++) {
        int buf = t & 1;
        #pragma unroll
        for (int gg = 0; gg < 4; gg++) {
            int kf = kh * 2 + (gg >> 1);
            int p = ami8 + 2 * (gg & 1);
            *(uint4*)&smw[aoffw(buf, kf, amf, p) + albA] = packh(pa[gg * 2], pa[gg * 2 + 1]);
        }
        #pragma unroll
        for (int g = 0; g < 4; g++) {
            int kf = bkh * 2 + (g >> 1);
            int r = g & 1;
            *(uint4*)&smw[boffw_gu(buf, kf, bnf, r, sel) + blbB] = pb[g];
        }
        __syncthreads();
        if (t + 1 < NT) {
            const float4* xp = xrow4 + (t + 1) * 16;
            #pragma unroll
            for (int i = 0; i < 8; i++) pa[i] = xp[i];
            const uint4* bp = brow4 + (t + 1) * 8;
            #pragma unroll
            for (int i = 0; i < 4; i++) pb[i] = bp[i];
        }
        #pragma unroll
        for (int kf = 0; kf < 4; kf++) {
            uint32_t a[2][4], bg[4][2], bu[4][2];
            #pragma unroll
            for (int mf = 0; mf < 2; mf++)
                #pragma unroll
                for (int r = 0; r < 4; r++)
                    a[mf][r] = smw[aoffw(buf, kf, wm * 2 + mf, r) + lane];
            #pragma unroll
            for (int nf = 0; nf < 4; nf++)
                #pragma unroll
                for (int r = 0; r < 2; r++) {
                    bg[nf][r] = smw[boffw_gu(buf, kf, wn * 4 + nf, r, 0) + lane];
                    bu[nf][r] = smw[boffw_gu(buf, kf, wn * 4 + nf, r, 1) + lane];
                }
            #pragma unroll
            for (int mf = 0; mf < 2; mf++)
                #pragma unroll
                for (int nf = 0; nf < 4; nf++) {
                    mma16(accG[mf][nf], a[mf], bg[nf]);
                    mma16(accU[mf][nf], a[mf], bu[nf]);
                }
        }
    }

    #pragma unroll
    for (int mf = 0; mf < 2; mf++) {
        #pragma unroll
        for (int hh = 0; hh < 2; hh++) {
            int row = wm * 32 + mf * 16 + (lane >> 2) + hh * 8;
            __half* orow = g_sh + (size_t)(m0 + row) * ISH_ + n0;
            #pragma unroll
            for (int nf = 0; nf < 4; nf++) {
                int col = wn * 32 + nf * 8 + (lane & 3) * 2;
                float vx = silu_mul(accG[mf][nf][hh * 2],     accU[mf][nf][hh * 2]);
                float vy = silu_mul(accG[mf][nf][hh * 2 + 1], accU[mf][nf][hh * 2 + 1]);
                *(uint32_t*)(orow + col) = f2h2(vx, vy);
            }
        }
    }
}

// ================= shared down + final combine =================
__global__ __launch_bounds__(256, 2) void shared_down_mma(float* __restrict__ out)
{
    extern __shared__ uint32_t smw[];
    int m0 = blockIdx.y * 128;
    int n0 = blockIdx.x * 128;
    int tid = threadIdx.x;

    int fm = tid & 127, kh = tid >> 7;
    const uint4* arow4 = (const uint4*)(g_sh + (size_t)(m0 + fm) * ISH_ + kh * 32);
    int amf = fm >> 4, ami8 = (fm & 15) >> 3, albA = 4 * (fm & 7);

    int fn = tid & 127, bkh = tid >> 7;
    const uint4* brow4 = (const uint4*)(g_sdwT + (size_t)(n0 + fn) * ISH_ + bkh * 32);
    int bnf = fn >> 3, blbB = 4 * (fn & 7);

    int w = tid >> 5, lane = tid & 31;
    int wm = w & 1, wn = w >> 1;

    float acc[4][4][4] = {};

    uint4 pa[4], pb[4];
    {
        #pragma unroll
        for (int i = 0; i < 4; i++) { pa[i] = arow4[i]; pb[i] = brow4[i]; }
    }

    const int NT = ISH_ / 64;  // 44
    for (int t = 0; t < NT; t++) {
        int buf = t & 1;
        #pragma unroll
        for (int g = 0; g < 4; g++) {
            int kf = kh * 2 + (g >> 1);
            int p = ami8 + 2 * (g & 1);
            *(uint4*)&smw[aoffw(buf, kf, amf, p) + albA] = pa[g];
        }
        #pragma unroll
        for (int g = 0; g < 4; g++) {
            int kf = bkh * 2 + (g >> 1);
            int r = g & 1;
            *(uint4*)&smw[boffw_dn(buf, kf, bnf, r) + blbB] = pb[g];
        }
        __syncthreads();
        if (t + 1 < NT) {
            const uint4* ap = arow4 + (t + 1) * 8;
            const uint4* bp = brow4 + (t + 1) * 8;
            #pragma unroll
            for (int i = 0; i < 4; i++) { pa[i] = ap[i]; pb[i] = bp[i]; }
        }
        #pragma unroll
        for (int kf = 0; kf < 4; kf++) {
            uint32_t a[4][4], b[4][2];
            #pragma unroll
            for (int mf = 0; mf < 4; mf++)
                #pragma unroll
                for (int r = 0; r < 4; r++)
                    a[mf][r] = smw[aoffw(buf, kf, wm * 4 + mf, r) + lane];
            #pragma unroll
            for (int nf = 0; nf < 4; nf++)
                #pragma unroll
                for (int r = 0; r < 2; r++)
                    b[nf][r] = smw[boffw_dn(buf, kf, wn * 4 + nf, r) + lane];
            #pragma unroll
            for (int mf = 0; mf < 4; mf++)
                #pragma unroll
                for (int nf = 0; nf < 4; nf++)
                    mma16(acc[mf][nf], a[mf], b[nf]);
        }
    }

    #pragma unroll
    for (int mf = 0; mf < 4; mf++) {
        #pragma unroll
        for (int hh = 0; hh < 2; hh++) {
            int row = wm * 64 + mf * 16 + (lane >> 2) + hh * 8;
            int tk = m0 + row;
            int p0 = g_pair_pos[tk][0], p1 = g_pair_pos[tk][1];
            int p2 = g_pair_pos[tk][2], p3 = g_pair_pos[tk][3];
            float* orow = out + (size_t)tk * H_ + n0;
            #pragma unroll
            for (int nf = 0; nf < 4; nf++) {
                int col = wn * 32 + nf * 8 + (lane & 3) * 2;
                float2 y0 = *(const float2*)(g_y + (size_t)p0 * H_ + n0 + col);
                float2 y1 = *(const float2*)(g_y + (size_t)p1 * H_ + n0 + col);
                float2 y2 = *(const float2*)(g_y + (size_t)p2 * H_ + n0 + col);
                float2 y3 = *(const float2*)(g_y + (size_t)p3 * H_ + n0 + col);
                float2 v;
                v.x = acc[mf][nf][hh * 2]     + y0.x + y1.x + y2.x + y3.x;
                v.y = acc[mf][nf][hh * 2 + 1] + y0.y + y1.y + y2.y + y3.y;
                *(float2*)(orow + col) = v;
            }
        }
    }
}

// ---------------- launch ----------------
extern "C" void kernel_launch(void* const* d_in, const int* in_sizes, int n_in,
                              void* d_out, int out_size)
{
    const float* x   = (const float*)d_in[0];
    const float* gw  = (const float*)d_in[1];
    const int*   gq  = (const int*)  d_in[2];
    const int*   gz  = (const int*)  d_in[3];
    const float* gs  = (const float*)d_in[4];
    const int*   uq  = (const int*)  d_in[5];
    const int*   uz  = (const int*)  d_in[6];
    const float* us  = (const float*)d_in[7];
    const int*   dq  = (const int*)  d_in[8];
    const int*   dz  = (const int*)  d_in[9];
    const float* ds  = (const float*)d_in[10];
    const float* sgw = (const float*)d_in[11];
    const float* suw = (const float*)d_in[12];
    const float* sdw = (const float*)d_in[13];
    float* out = (float*)d_out;

    static bool attr_done = false;
    if (!attr_done) {
        cudaFuncSetAttribute(expert_gu_mma,   cudaFuncAttributeMaxDynamicSharedMemorySize, SMEM_BYTES);
        cudaFuncSetAttribute(expert_down_mma, cudaFuncAttributeMaxDynamicSharedMemorySize, SMEM_BYTES);
        cudaFuncSetAttribute(shared_gu_mma,   cudaFuncAttributeMaxDynamicSharedMemorySize, SMEM_BYTES);
        cudaFuncSetAttribute(shared_down_mma, cudaFuncAttributeMaxDynamicSharedMemorySize, SMEM_BYTES);
        attr_done = true;
    }

    zero_kernel<<<1, 32>>>();
    router_kernel<<<T_, 256>>>(x, gw);
    scan_kernel<<<1, 32>>>();
    scatter_kernel<<<(T_ + 255) / 256, 256>>>();

    __half* sgwT; cudaGetSymbolAddress((void**)&sgwT, g_sgwT);
    __half* suwT; cudaGetSymbolAddress((void**)&suwT, g_suwT);
    __half* sdwT; cudaGetSymbolAddress((void**)&sdwT, g_sdwT);
    transpose_half<<<dim3(ISH_ / 32, H_ / 32), dim3(32, 8)>>>(sgw, sgwT, H_, ISH_);
    transpose_half<<<dim3(ISH_ / 32, H_ / 32), dim3(32, 8)>>>(suw, suwT, H_, ISH_);
    transpose_half<<<dim3(H_ / 32, ISH_ / 32), dim3(32, 8)>>>(sdw, sdwT, ISH_, H_);

    dim3 ggu(I_ / 64, T_ / 128, E_);       // (22, 8, 32)
    expert_gu_mma<<<ggu, 256, SMEM_BYTES>>>(x, gq, gz, gs, uq, uz, us);

    dim3 gdn(H_ / 128, T_ / 128, E_);      // (16, 8, 32)
    expert_down_mma<<<gdn, 256, SMEM_BYTES>>>(dq, dz, ds);

    dim3 gsg(ISH_ / 64, T_ / 128);         // (44, 8)
    shared_gu_mma<<<gsg, 256, SMEM_BYTES>>>(x);

    dim3 gsd(H_ / 128, T_ / 128);          // (16, 8)
    shared_down_mma<<<gsd, 256, SMEM_BYTES>>>(out);
}

// round 8
// speedup vs baseline: 3.8024x; 1.1952x over previous
#include <cuda_runtime.h>
#include <cuda_fp16.h>
#include <math.h>
#include <stdint.h>

#define E_    32
#define TOPK  4
#define H_    2048
#define I_    1408
#define GS_   128
#define T_    1024
#define ISH_  2816
#define NPAIR (T_*TOPK)

// ---------------- device scratch ----------------
__device__ int    g_counts[E_];
__device__ int    g_offsets[E_];
__device__ int    g_cursor[E_];
__device__ int    g_topk_idx[T_][TOPK];
__device__ float  g_topk_w[T_][TOPK];
__device__ int    g_pair_token[NPAIR];
__device__ float  g_pair_w[NPAIR];
__device__ int    g_pair_pos[T_][TOPK];
__device__ __half g_xh[(size_t)T_ * H_];
__device__ __half g_h[(size_t)NPAIR * I_];
__device__ float  g_y[(size_t)NPAIR * H_];
__device__ __half g_sh[(size_t)T_ * ISH_];
__device__ __half g_sgwT[(size_t)ISH_ * H_];   // [ISH][H]
__device__ __half g_suwT[(size_t)ISH_ * H_];   // [ISH][H]
__device__ __half g_sdwT[(size_t)H_ * ISH_];   // [H][ISH]

// ---------------- helpers ----------------
__device__ __forceinline__ uint32_t smem_u32(const void* p) {
    uint32_t a;
    asm("{ .reg .u64 t; cvta.to.shared.u64 t, %1; cvt.u32.u64 %0, t; }" : "=r"(a) : "l"(p));
    return a;
}
#define CP16(dst, src) asm volatile("cp.async.ca.shared.global [%0], [%1], 16;\n" :: "r"(dst), "l"(src))
#define CP_COMMIT()    asm volatile("cp.async.commit_group;\n" ::: "memory")
#define CP_WAIT0()     asm volatile("cp.async.wait_group 0;\n" ::: "memory")

__device__ __forceinline__ uint32_t f2h2(float a, float b) {
    __half2 h;
    h.x = __float2half_rn(a);
    h.y = __float2half_rn(b);
    return *(uint32_t*)&h;
}
__device__ __forceinline__ uint32_t dqh2(unsigned w, int sh, float s, float zs) {
    float v0 = fmaf((float)((w >> sh) & 15), s, -zs);
    float v1 = fmaf((float)((w >> (sh + 4)) & 15), s, -zs);
    return f2h2(v0, v1);
}
__device__ __forceinline__ uint4 dqw(unsigned w, float s, float zs) {
    uint4 v;
    v.x = dqh2(w, 0, s, zs);  v.y = dqh2(w, 8, s, zs);
    v.z = dqh2(w, 16, s, zs); v.w = dqh2(w, 24, s, zs);
    return v;
}
__device__ __forceinline__ void mma16(float* d, const uint32_t* a, const uint32_t* b) {
    asm volatile("mma.sync.aligned.m16n8k16.row.col.f32.f16.f16.f32 "
        "{%0,%1,%2,%3},{%4,%5,%6,%7},{%8,%9},{%0,%1,%2,%3};\n"
        : "+f"(d[0]), "+f"(d[1]), "+f"(d[2]), "+f"(d[3])
        : "r"(a[0]), "r"(a[1]), "r"(a[2]), "r"(a[3]), "r"(b[0]), "r"(b[1]));
}
__device__ __forceinline__ float silu_mul(float g, float u) {
    return g / (1.f + __expf(-g)) * u;
}

// smem word layout per buffer (8192 words = 32KB), BK=64:
//  A 128x64: [kf4][mf8][plane4][lane32] = 4096 words
//  B gu: 2 sel x [kf4][nf8][r2][lane32] = 4096 ; B dn: [kf4][nf16][r2][lane32] = 4096
__device__ __forceinline__ int aoffw(int buf, int kf, int mf, int p) {
    return buf * 8192 + ((kf * 8 + mf) * 4 + p) * 32;
}
__device__ __forceinline__ int boffw_gu(int buf, int kf, int nf, int r, int sel) {
    return buf * 8192 + 4096 + sel * 2048 + ((kf * 8 + nf) * 2 + r) * 32;
}
__device__ __forceinline__ int boffw_dn(int buf, int kf, int nf, int r) {
    return buf * 8192 + 4096 + ((kf * 16 + nf) * 2 + r) * 32;
}
#define AUXW 16384
#define SMEM_BYTES ((16384 + 128) * 4)

// ---------------- small kernels ----------------
__global__ void zero_kernel() {
    int i = threadIdx.x;
    if (i < E_) g_counts[i] = 0;
}

__global__ void router_kernel(const float* __restrict__ x, const float* __restrict__ gw) {
    __shared__ float xs[H_];
    __shared__ float part[8][E_];
    __shared__ float scores[E_];
    int t = blockIdx.x;
    for (int h = threadIdx.x; h < H_; h += 256) {
        float v = x[t * H_ + h];
        xs[h] = v;
        g_xh[(size_t)t * H_ + h] = __float2half_rn(v);
    }
    __syncthreads();
    int e = threadIdx.x & 31;
    int hh = threadIdx.x >> 5;
    float acc = 0.f;
    for (int h = hh; h < H_; h += 8) acc += xs[h] * gw[h * E_ + e];
    part[hh][e] = acc;
    __syncthreads();
    if (threadIdx.x < E_) {
        float s = 0.f;
        #pragma unroll
        for (int i = 0; i < 8; i++) s += part[i][threadIdx.x];
        scores[threadIdx.x] = 1.f / (1.f + expf(-s));
    }
    __syncthreads();
    if (threadIdx.x == 0) {
        bool used[E_];
        #pragma unroll
        for (int i = 0; i < E_; i++) used[i] = false;
        float v[TOPK]; int id[TOPK];
        float sum = 0.f;
        for (int j = 0; j < TOPK; j++) {
            float best = -1e30f; int bi = 0;
            for (int ee = 0; ee < E_; ee++)
                if (!used[ee] && scores[ee] > best) { best = scores[ee]; bi = ee; }
            used[bi] = true; v[j] = best; id[j] = bi; sum += best;
        }
        float inv = 2.5f / (sum + 1e-20f);
        for (int j = 0; j < TOPK; j++) {
            g_topk_idx[t][j] = id[j];
            g_topk_w[t][j] = v[j] * inv;
            atomicAdd(&g_counts[id[j]], 1);
        }
    }
}

__global__ void scan_scatter_kernel() {
    int tid = threadIdx.x;
    if (tid == 0) {
        int off = 0;
        for (int e = 0; e < E_; e++) {
            g_offsets[e] = off; g_cursor[e] = off; off += g_counts[e];
        }
    }
    __syncthreads();
    int t = tid;  // 1024 threads
    for (int j = 0; j < TOPK; j++) {
        int e = g_topk_idx[t][j];
        int pos = atomicAdd(&g_cursor[e], 1);
        g_pair_token[pos] = t;
        g_pair_w[pos] = g_topk_w[t][j];
        g_pair_pos[t][j] = pos;
    }
}

// in[R][C] fp32 -> out[C][R] half
__global__ void transpose_half(const float* __restrict__ in, __half* __restrict__ out, int R, int C) {
    __shared__ float tile[32][33];
    int c0 = blockIdx.x * 32, r0 = blockIdx.y * 32;
    for (int i = threadIdx.y; i < 32; i += 8)
        tile[i][threadIdx.x] = in[(size_t)(r0 + i) * C + c0 + threadIdx.x];
    __syncthreads();
    for (int i = threadIdx.y; i < 32; i += 8)
        out[(size_t)(c0 + i) * R + r0 + threadIdx.x] = __float2half_rn(tile[threadIdx.x][i]);
}

// ================= expert gate/up: h = silu(X Wg^T) * (X Wu^T) =================
// block 128(M) x 64(N), BK=64, 256 threads, warp tile 32x32 (4 M x 2 N warps)
__global__ __launch_bounds__(256, 2) void expert_gu_mma(
    const int* __restrict__ gq, const int* __restrict__ gz, const float* __restrict__ gs,
    const int* __restrict__ uq, const int* __restrict__ uz, const float* __restrict__ us)
{
    extern __shared__ uint32_t smw[];
    int e = blockIdx.z;
    int cnt = g_counts[e];
    int m0 = blockIdx.y * 128;
    if (m0 >= cnt) return;
    int off = g_offsets[e];
    int n0 = blockIdx.x * 64;
    int tid = threadIdx.x;
    uint32_t smb = smem_u32(smw);

    int* toks = (int*)&smw[AUXW];
    if (tid < 128) {
        int m = m0 + tid;
        toks[tid] = (m < cnt) ? g_pair_token[off + m] : 0;
    }
    __syncthreads();

    // A fill (cp.async, shared-space addresses): row fm, k-half kh
    int fm = tid & 127, kh = tid >> 7;
    const __half* xrow = g_xh + (size_t)toks[fm] * H_ + kh * 32;
    int amf = fm >> 4, ami8 = (fm & 15) >> 3, albA = 4 * (fm & 7);
    uint32_t adst[4];
    #pragma unroll
    for (int gg = 0; gg < 4; gg++)
        adst[gg] = smb + 4 * (aoffw(0, kh * 2 + (gg >> 1), amf, ami8 + 2 * (gg & 1)) + albA);
    // B fill (dequant regs, generic word-index stores): sel, row fn, k-half bkh
    int sel = tid >> 7;
    int t2 = tid & 127;
    int fn = t2 & 63, bkh = t2 >> 6;
    long rowb = (long)e * I_ + n0 + fn;
    const int4*  qr4 = (const int4*)((sel ? uq : gq) + rowb * (H_ / 8));
    const int*   zr  = (sel ? uz : gz) + rowb * (H_ / GS_);
    const float* sr  = (sel ? us : gs) + rowb * (H_ / GS_);
    int bnf = fn >> 3, blbB = 4 * (fn & 7);
    int bwi[4];
    #pragma unroll
    for (int wi = 0; wi < 4; wi++)
        bwi[wi] = boffw_gu(0, bkh * 2 + (wi >> 1), bnf, wi & 1, sel) + blbB;

    int w = tid >> 5, lane = tid & 31;
    int wm = w & 3, wn = w >> 2;

    float accG[2][4][4] = {};
    float accU[2][4][4] = {};

    const int NT = H_ / 64;  // 32
    int4 pq; float ps, pz;
    // prologue: fill tile0 -> buf0
    pq = qr4[bkh]; ps = sr[0]; pz = (float)zr[0] * ps;
    #pragma unroll
    for (int gg = 0; gg < 4; gg++) CP16(adst[gg], xrow + gg * 8);
    CP_COMMIT();
    {
        unsigned wd[4] = {(unsigned)pq.x, (unsigned)pq.y, (unsigned)pq.z, (unsigned)pq.w};
        #pragma unroll
        for (int wi = 0; wi < 4; wi++) *(uint4*)&smw[bwi[wi]] = dqw(wd[wi], ps, pz);
    }
    pq = qr4[2 + bkh]; ps = sr[0]; pz = (float)zr[0] * ps;  // regs for tile1 (gi=0)
    CP_WAIT0();
    __syncthreads();

    for (int t = 0; t < NT; t++) {
        int buf = t & 1;
        int wo = (buf ^ 1) * 8192;        // word offset of other buffer
        uint32_t bo = (buf ^ 1) * 32768;  // byte offset of other buffer
        if (t + 1 < NT) {
            const __half* xs = xrow + (t + 1) * 64;
            #pragma unroll
            for (int gg = 0; gg < 4; gg++) CP16(adst[gg] + bo, xs + gg * 8);
            CP_COMMIT();
            unsigned wd[4] = {(unsigned)pq.x, (unsigned)pq.y, (unsigned)pq.z, (unsigned)pq.w};
            #pragma unroll
            for (int wi = 0; wi < 4; wi++) *(uint4*)&smw[bwi[wi] + wo] = dqw(wd[wi], ps, pz);
            int tn = (t + 2 < NT) ? (t + 2) : (NT - 1);
            int gi = tn >> 1;
            pq = qr4[tn * 2 + bkh]; ps = sr[gi]; pz = (float)zr[gi] * ps;
        }
        #pragma unroll
        for (int kf = 0; kf < 4; kf++) {
            uint32_t a[2][4], bg[4][2], bu[4][2];
            #pragma unroll
            for (int mf = 0; mf < 2; mf++)
                #pragma unroll
                for (int r = 0; r < 4; r++)
                    a[mf][r] = smw[aoffw(buf, kf, wm * 2 + mf, r) + lane];
            #pragma unroll
            for (int nf = 0; nf < 4; nf++)
                #pragma unroll
                for (int r = 0; r < 2; r++) {
                    bg[nf][r] = smw[boffw_gu(buf, kf, wn * 4 + nf, r, 0) + lane];
                    bu[nf][r] = smw[boffw_gu(buf, kf, wn * 4 + nf, r, 1) + lane];
                }
            #pragma unroll
            for (int mf = 0; mf < 2; mf++)
                #pragma unroll
                for (int nf = 0; nf < 4; nf++) {
                    mma16(accG[mf][nf], a[mf], bg[nf]);
                    mma16(accU[mf][nf], a[mf], bu[nf]);
                }
        }
        if (t + 1 < NT) CP_WAIT0();
        __syncthreads();
    }

    #pragma unroll
    for (int mf = 0; mf < 2; mf++) {
        #pragma unroll
        for (int hh = 0; hh < 2; hh++) {
            int row = wm * 32 + mf * 16 + (lane >> 2) + hh * 8;
            if (m0 + row < cnt) {
                __half* orow = g_h + (size_t)(off + m0 + row) * I_ + n0;
                #pragma unroll
                for (int nf = 0; nf < 4; nf++) {
                    int col = wn * 32 + nf * 8 + (lane & 3) * 2;
                    float vx = silu_mul(accG[mf][nf][hh * 2],     accU[mf][nf][hh * 2]);
                    float vy = silu_mul(accG[mf][nf][hh * 2 + 1], accU[mf][nf][hh * 2 + 1]);
                    *(uint32_t*)(orow + col) = f2h2(vx, vy);
                }
            }
        }
    }
}

// ================= expert down: y = pw * (h @ Wd^T) =================
// block 128(M) x 128(N), BK=64, warp tile 64x32 (2 M x 4 N)
__global__ __launch_bounds__(256, 2) void expert_down_mma(
    const int* __restrict__ dq, const int* __restrict__ dz, const float* __restrict__ ds)
{
    extern __shared__ uint32_t smw[];
    int e = blockIdx.z;
    int cnt = g_counts[e];
    int m0 = blockIdx.y * 128;
    if (m0 >= cnt) return;
    int off = g_offsets[e];
    int n0 = blockIdx.x * 128;
    int tid = threadIdx.x;
    uint32_t smb = smem_u32(smw);

    float* pwv = (float*)&smw[AUXW];
    if (tid < 128) {
        int m = m0 + tid;
        pwv[tid] = (m < cnt) ? g_pair_w[off + m] : 0.f;
    }
    __syncthreads();

    int fm = tid & 127, kh = tid >> 7;
    size_t ar = (size_t)off + ((m0 + fm < cnt) ? (m0 + fm) : 0);
    const __half* hrow = g_h + ar * I_ + kh * 32;
    int amf = fm >> 4, ami8 = (fm & 15) >> 3, albA = 4 * (fm & 7);
    uint32_t adst[4];
    #pragma unroll
    for (int gg = 0; gg < 4; gg++)
        adst[gg] = smb + 4 * (aoffw(0, kh * 2 + (gg >> 1), amf, ami8 + 2 * (gg & 1)) + albA);

    int fn = tid & 127, bkh = tid >> 7;
    long rowb = (long)e * H_ + n0 + fn;
    const int4*  qr4 = (const int4*)(dq + rowb * (I_ / 8));
    const int*   zr  = dz + rowb * (I_ / GS_);
    const float* sr  = ds + rowb * (I_ / GS_);
    int bnf = fn >> 3, blbB = 4 * (fn & 7);
    int bwi[4];
    #pragma unroll
    for (int wi = 0; wi < 4; wi++)
        bwi[wi] = boffw_dn(0, bkh * 2 + (wi >> 1), bnf, wi & 1) + blbB;

    int w = tid >> 5, lane = tid & 31;
    int wm = w & 1, wn = w >> 1;

    float acc[4][4][4] = {};

    const int NT = I_ / 64;  // 22
    int4 pq; float ps, pz;
    pq = qr4[bkh]; ps = sr[0]; pz = (float)zr[0] * ps;
    #pragma unroll
    for (int gg = 0; gg < 4; gg++) CP16(adst[gg], hrow + gg * 8);
    CP_COMMIT();
    {
        unsigned wd[4] = {(unsigned)pq.x, (unsigned)pq.y, (unsigned)pq.z, (unsigned)pq.w};
        #pragma unroll
        for (int wi = 0; wi < 4; wi++) *(uint4*)&smw[bwi[wi]] = dqw(wd[wi], ps, pz);
    }
    pq = qr4[2 + bkh]; ps = sr[0]; pz = (float)zr[0] * ps;
    CP_WAIT0();
    __syncthreads();

    for (int t = 0; t < NT; t++) {
        int buf = t & 1;
        int wo = (buf ^ 1) * 8192;
        uint32_t bo = (buf ^ 1) * 32768;
        if (t + 1 < NT) {
            const __half* hs = hrow + (t + 1) * 64;
            #pragma unroll
            for (int gg = 0; gg < 4; gg++) CP16(adst[gg] + bo, hs + gg * 8);
            CP_COMMIT();
            unsigned wd[4] = {(unsigned)pq.x, (unsigned)pq.y, (unsigned)pq.z, (unsigned)pq.w};
            #pragma unroll
            for (int wi = 0; wi < 4; wi++) *(uint4*)&smw[bwi[wi] + wo] = dqw(wd[wi], ps, pz);
            int tn = (t + 2 < NT) ? (t + 2) : (NT - 1);
            int gi = (tn * 64) / GS_;
            pq = qr4[tn * 2 + bkh]; ps = sr[gi]; pz = (float)zr[gi] * ps;
        }
        #pragma unroll
        for (int kf = 0; kf < 4; kf++) {
            uint32_t a[4][4], b[4][2];
            #pragma unroll
            for (int mf = 0; mf < 4; mf++)
                #pragma unroll
                for (int r = 0; r < 4; r++)
                    a[mf][r] = smw[aoffw(buf, kf, wm * 4 + mf, r) + lane];
            #pragma unroll
            for (int nf = 0; nf < 4; nf++)
                #pragma unroll
                for (int r = 0; r < 2; r++)
                    b[nf][r] = smw[boffw_dn(buf, kf, wn * 4 + nf, r) + lane];
            #pragma unroll
            for (int mf = 0; mf < 4; mf++)
                #pragma unroll
                for (int nf = 0; nf < 4; nf++)
                    mma16(acc[mf][nf], a[mf], b[nf]);
        }
        if (t + 1 < NT) CP_WAIT0();
        __syncthreads();
    }

    #pragma unroll
    for (int mf = 0; mf < 4; mf++) {
        #pragma unroll
        for (int hh = 0; hh < 2; hh++) {
            int row = wm * 64 + mf * 16 + (lane >> 2) + hh * 8;
            if (m0 + row < cnt) {
                float wgt = pwv[row];
                float* orow = g_y + (size_t)(off + m0 + row) * H_ + n0;
                #pragma unroll
                for (int nf = 0; nf < 4; nf++) {
                    int col = wn * 32 + nf * 8 + (lane & 3) * 2;
                    float2 v;
                    v.x = wgt * acc[mf][nf][hh * 2];
                    v.y = wgt * acc[mf][nf][hh * 2 + 1];
                    *(float2*)(orow + col) = v;
                }
            }
        }
    }
}

// ================= shared gate/up (fully async fills) =================
__global__ __launch_bounds__(256, 2) void shared_gu_mma()
{
    extern __shared__ uint32_t smw[];
    int m0 = blockIdx.y * 128;
    int n0 = blockIdx.x * 64;
    int tid = threadIdx.x;
    uint32_t smb = smem_u32(smw);

    int fm = tid & 127, kh = tid >> 7;
    const __half* xrow = g_xh + (size_t)(m0 + fm) * H_ + kh * 32;
    int amf = fm >> 4, ami8 = (fm & 15) >> 3, albA = 4 * (fm & 7);
    uint32_t adst[4];
    #pragma unroll
    for (int gg = 0; gg < 4; gg++)
        adst[gg] = smb + 4 * (aoffw(0, kh * 2 + (gg >> 1), amf, ami8 + 2 * (gg & 1)) + albA);

    int sel = tid >> 7;
    int t2 = tid & 127;
    int fn = t2 & 63, bkh = t2 >> 6;
    const __half* brow = (sel ? g_suwT : g_sgwT) + (size_t)(n0 + fn) * H_ + bkh * 32;
    int bnf = fn >> 3, blbB = 4 * (fn & 7);
    uint32_t bdst[4];
    #pragma unroll
    for (int wi = 0; wi < 4; wi++)
        bdst[wi] = smb + 4 * (boffw_gu(0, bkh * 2 + (wi >> 1), bnf, wi & 1, sel) + blbB);

    int w = tid >> 5, lane = tid & 31;
    int wm = w & 3, wn = w >> 2;

    float accG[2][4][4] = {};
    float accU[2][4][4] = {};

    const int NT = H_ / 64;  // 32
    #pragma unroll
    for (int gg = 0; gg < 4; gg++) {
        CP16(adst[gg], xrow + gg * 8);
        CP16(bdst[gg], brow + gg * 8);
    }
    CP_COMMIT();
    CP_WAIT0();
    __syncthreads();

    for (int t = 0; t < NT; t++) {
        int buf = t & 1;
        uint32_t bo = (buf ^ 1) * 32768;
        if (t + 1 < NT) {
            const __half* xs = xrow + (t + 1) * 64;
            const __half* bs = brow + (t + 1) * 64;
            #pragma unroll
            for (int gg = 0; gg < 4; gg++) {
                CP16(adst[gg] + bo, xs + gg * 8);
                CP16(bdst[gg] + bo, bs + gg * 8);
            }
            CP_COMMIT();
        }
        #pragma unroll
        for (int kf = 0; kf < 4; kf++) {
            uint32_t a[2][4], bg[4][2], bu[4][2];
            #pragma unroll
            for (int mf = 0; mf < 2; mf++)
                #pragma unroll
                for (int r = 0; r < 4; r++)
                    a[mf][r] = smw[aoffw(buf, kf, wm * 2 + mf, r) + lane];
            #pragma unroll
            for (int nf = 0; nf < 4; nf++)
                #pragma unroll
                for (int r = 0; r < 2; r++) {
                    bg[nf][r] = smw[boffw_gu(buf, kf, wn * 4 + nf, r, 0) + lane];
                    bu[nf][r] = smw[boffw_gu(buf, kf, wn * 4 + nf, r, 1) + lane];
                }
            #pragma unroll
            for (int mf = 0; mf < 2; mf++)
                #pragma unroll
                for (int nf = 0; nf < 4; nf++) {
                    mma16(accG[mf][nf], a[mf], bg[nf]);
                    mma16(accU[mf][nf], a[mf], bu[nf]);
                }
        }
        if (t + 1 < NT) CP_WAIT0();
        __syncthreads();
    }

    #pragma unroll
    for (int mf = 0; mf < 2; mf++) {
        #pragma unroll
        for (int hh = 0; hh < 2; hh++) {
            int row = wm * 32 + mf * 16 + (lane >> 2) + hh * 8;
            __half* orow = g_sh + (size_t)(m0 + row) * ISH_ + n0;
            #pragma unroll
            for (int nf = 0; nf < 4; nf++) {
                int col = wn * 32 + nf * 8 + (lane & 3) * 2;
                float vx = silu_mul(accG[mf][nf][hh * 2],     accU[mf][nf][hh * 2]);
                float vy = silu_mul(accG[mf][nf][hh * 2 + 1], accU[mf][nf][hh * 2 + 1]);
                *(uint32_t*)(orow + col) = f2h2(vx, vy);
            }
        }
    }
}

// ================= shared down + final combine (fully async fills) =================
__global__ __launch_bounds__(256, 2) void shared_down_mma(float* __restrict__ out)
{
    extern __shared__ uint32_t smw[];
    int m0 = blockIdx.y * 128;
    int n0 = blockIdx.x * 128;
    int tid = threadIdx.x;
    uint32_t smb = smem_u32(smw);

    int fm = tid & 127, kh = tid >> 7;
    const __half* arow = g_sh + (size_t)(m0 + fm) * ISH_ + kh * 32;
    int amf = fm >> 4, ami8 = (fm & 15) >> 3, albA = 4 * (fm & 7);
    uint32_t adst[4];
    #pragma unroll
    for (int gg = 0; gg < 4; gg++)
        adst[gg] = smb + 4 * (aoffw(0, kh * 2 + (gg >> 1), amf, ami8 + 2 * (gg & 1)) + albA);

    int fn = tid & 127, bkh = tid >> 7;
    const __half* brow = g_sdwT + (size_t)(n0 + fn) * ISH_ + bkh * 32;
    int bnf = fn >> 3, blbB = 4 * (fn & 7);
    uint32_t bdst[4];
    #pragma unroll
    for (int wi = 0; wi < 4; wi++)
        bdst[wi] = smb + 4 * (boffw_dn(0, bkh * 2 + (wi >> 1), bnf, wi & 1) + blbB);

    int w = tid >> 5, lane = tid & 31;
    int wm = w & 1, wn = w >> 1;

    float acc[4][4][4] = {};

    const int NT = ISH_ / 64;  // 44
    #pragma unroll
    for (int gg = 0; gg < 4; gg++) {
        CP16(adst[gg], arow + gg * 8);
        CP16(bdst[gg], brow + gg * 8);
    }
    CP_COMMIT();
    CP_WAIT0();
    __syncthreads();

    for (int t = 0; t < NT; t++) {
        int buf = t & 1;
        uint32_t bo = (buf ^ 1) * 32768;
        if (t + 1 < NT) {
            const __half* as = arow + (t + 1) * 64;
            const __half* bs = brow + (t + 1) * 64;
            #pragma unroll
            for (int gg = 0; gg < 4; gg++) {
                CP16(adst[gg] + bo, as + gg * 8);
                CP16(bdst[gg] + bo, bs + gg * 8);
            }
            CP_COMMIT();
        }
        #pragma unroll
        for (int kf = 0; kf < 4; kf++) {
            uint32_t a[4][4], b[4][2];
            #pragma unroll
            for (int mf = 0; mf < 4; mf++)
                #pragma unroll
                for (int r = 0; r < 4; r++)
                    a[mf][r] = smw[aoffw(buf, kf, wm * 4 + mf, r) + lane];
            #pragma unroll
            for (int nf = 0; nf < 4; nf++)
                #pragma unroll
                for (int r = 0; r < 2; r++)
                    b[nf][r] = smw[boffw_dn(buf, kf, wn * 4 + nf, r) + lane];
            #pragma unroll
            for (int mf = 0; mf < 4; mf++)
                #pragma unroll
                for (int nf = 0; nf < 4; nf++)
                    mma16(acc[mf][nf], a[mf], b[nf]);
        }
        if (t + 1 < NT) CP_WAIT0();
        __syncthreads();
    }

    #pragma unroll
    for (int mf = 0; mf < 4; mf++) {
        #pragma unroll
        for (int hh = 0; hh < 2; hh++) {
            int row = wm * 64 + mf * 16 + (lane >> 2) + hh * 8;
            int tk = m0 + row;
            int p0 = g_pair_pos[tk][0], p1 = g_pair_pos[tk][1];
            int p2 = g_pair_pos[tk][2], p3 = g_pair_pos[tk][3];
            float* orow = out + (size_t)tk * H_ + n0;
            #pragma unroll
            for (int nf = 0; nf < 4; nf++) {
                int col = wn * 32 + nf * 8 + (lane & 3) * 2;
                float2 y0 = *(const float2*)(g_y + (size_t)p0 * H_ + n0 + col);
                float2 y1 = *(const float2*)(g_y + (size_t)p1 * H_ + n0 + col);
                float2 y2 = *(const float2*)(g_y + (size_t)p2 * H_ + n0 + col);
                float2 y3 = *(const float2*)(g_y + (size_t)p3 * H_ + n0 + col);
                float2 v;
                v.x = acc[mf][nf][hh * 2]     + y0.x + y1.x + y2.x + y3.x;
                v.y = acc[mf][nf][hh * 2 + 1] + y0.y + y1.y + y2.y + y3.y;
                *(float2*)(orow + col) = v;
            }
        }
    }
}

// ---------------- launch ----------------
extern "C" void kernel_launch(void* const* d_in, const int* in_sizes, int n_in,
                              void* d_out, int out_size)
{
    const float* x   = (const float*)d_in[0];
    const float* gw  = (const float*)d_in[1];
    const int*   gq  = (const int*)  d_in[2];
    const int*   gz  = (const int*)  d_in[3];
    const float* gs  = (const float*)d_in[4];
    const int*   uq  = (const int*)  d_in[5];
    const int*   uz  = (const int*)  d_in[6];
    const float* us  = (const float*)d_in[7];
    const int*   dq  = (const int*)  d_in[8];
    const int*   dz  = (const int*)  d_in[9];
    const float* ds  = (const float*)d_in[10];
    const float* sgw = (const float*)d_in[11];
    const float* suw = (const float*)d_in[12];
    const float* sdw = (const float*)d_in[13];
    float* out = (float*)d_out;

    static bool attr_done = false;
    if (!attr_done) {
        cudaFuncSetAttribute(expert_gu_mma,   cudaFuncAttributeMaxDynamicSharedMemorySize, SMEM_BYTES);
        cudaFuncSetAttribute(expert_down_mma, cudaFuncAttributeMaxDynamicSharedMemorySize, SMEM_BYTES);
        cudaFuncSetAttribute(shared_gu_mma,   cudaFuncAttributeMaxDynamicSharedMemorySize, SMEM_BYTES);
        cudaFuncSetAttribute(shared_down_mma, cudaFuncAttributeMaxDynamicSharedMemorySize, SMEM_BYTES);
        attr_done = true;
    }

    zero_kernel<<<1, 32>>>();
    router_kernel<<<T_, 256>>>(x, gw);
    scan_scatter_kernel<<<1, 1024>>>();

    dim3 ggu(I_ / 64, T_ / 128, E_);       // (22, 8, 32)
    expert_gu_mma<<<ggu, 256, SMEM_BYTES>>>(gq, gz, gs, uq, uz, us);

    dim3 gdn(H_ / 128, T_ / 128, E_);      // (16, 8, 32)
    expert_down_mma<<<gdn, 256, SMEM_BYTES>>>(dq, dz, ds);

    __half* sgwT; cudaGetSymbolAddress((void**)&sgwT, g_sgwT);
    __half* suwT; cudaGetSymbolAddress((void**)&suwT, g_suwT);
    __half* sdwT; cudaGetSymbolAddress((void**)&sdwT, g_sdwT);
    transpose_half<<<dim3(ISH_ / 32, H_ / 32), dim3(32, 8)>>>(sgw, sgwT, H_, ISH_);
    transpose_half<<<dim3(ISH_ / 32, H_ / 32), dim3(32, 8)>>>(suw, suwT, H_, ISH_);
    transpose_half<<<dim3(H_ / 32, ISH_ / 32), dim3(32, 8)>>>(sdw, sdwT, ISH_, H_);

    dim3 gsg(ISH_ / 64, T_ / 128);         // (44, 8)
    shared_gu_mma<<<gsg, 256, SMEM_BYTES>>>();

    dim3 gsd(H_ / 128, T_ / 128);          // (16, 8)
    shared_down_mma<<<gsd, 256, SMEM_BYTES>>>(out);
}

// round 9
// speedup vs baseline: 3.8470x; 1.0117x over previous
#include <cuda_runtime.h>
#include <cuda_fp16.h>
#include <math.h>
#include <stdint.h>

#define E_    32
#define TOPK  4
#define H_    2048
#define I_    1408
#define GS_   128
#define T_    1024
#define ISH_  2816
#define NPAIR (T_*TOPK)

// K-dim storage permutation (within each 8-element group):
// storage position of logical index i:  r=i&7 -> ((r&3)<<1)|(r>>2)
__device__ __forceinline__ int PERM(int i) {
    int r = i & 7;
    return (i & ~7) | (((r & 3) << 1) | (r >> 2));
}

// ---------------- device scratch ----------------
__device__ int    g_counts[E_];
__device__ int    g_offsets[E_];
__device__ int    g_cursor[E_];
__device__ int    g_topk_idx[T_][TOPK];
__device__ float  g_topk_w[T_][TOPK];
__device__ int    g_pair_token[NPAIR];
__device__ float  g_pair_w[NPAIR];
__device__ int    g_pair_pos[T_][TOPK];
__device__ __half g_xh[(size_t)T_ * H_];      // H-dim PERM-stored
__device__ __half g_h[(size_t)NPAIR * I_];    // I-dim PERM-stored
__device__ float  g_y[(size_t)NPAIR * H_];
__device__ __half g_sh[(size_t)T_ * ISH_];    // ISH-dim PERM-stored
__device__ __half g_sgwT[(size_t)ISH_ * H_];  // [ISH][H], H PERM-stored
__device__ __half g_suwT[(size_t)ISH_ * H_];  // [ISH][H], H PERM-stored
__device__ __half g_sdwT[(size_t)H_ * ISH_];  // [H][ISH], ISH PERM-stored

// ---------------- helpers ----------------
__device__ __forceinline__ uint32_t smem_u32(const void* p) {
    uint32_t a;
    asm("{ .reg .u64 t; cvta.to.shared.u64 t, %1; cvt.u32.u64 %0, t; }" : "=r"(a) : "l"(p));
    return a;
}
#define CP16(dst, src) asm volatile("cp.async.ca.shared.global [%0], [%1], 16;\n" :: "r"(dst), "l"(src))
#define CP_COMMIT()    asm volatile("cp.async.commit_group;\n" ::: "memory")
#define CP_WAIT0()     asm volatile("cp.async.wait_group 0;\n" ::: "memory")

__device__ __forceinline__ uint32_t f2h2(float a, float b) {
    __half2 h;
    h.x = __float2half_rn(a);
    h.y = __float2half_rn(b);
    return *(uint32_t*)&h;
}
// magic-number half2 dequant: h holds (1024+c_lo, 1024+c_hi) bits
__device__ __forceinline__ uint32_t dq2(uint32_t h, uint32_t z2, uint32_t s2) {
    __half2 r = __hmul2(__hsub2(*(__half2*)&h, *(__half2*)&z2), *(__half2*)&s2);
    return *(uint32_t*)&r;
}
// one packed word (8 codes) -> 4 half2 in PERM order: (c0,c4)(c1,c5)(c2,c6)(c3,c7)
__device__ __forceinline__ uint4 dqw_h(unsigned w, uint32_t z2, uint32_t s2) {
    uint4 v;
    v.x = dq2(( w        & 0x000F000Fu) | 0x64006400u, z2, s2);
    v.y = dq2(((w >> 4 ) & 0x000F000Fu) | 0x64006400u, z2, s2);
    v.z = dq2(((w >> 8 ) & 0x000F000Fu) | 0x64006400u, z2, s2);
    v.w = dq2(((w >> 12) & 0x000F000Fu) | 0x64006400u, z2, s2);
    return v;
}
// build (z2, s2) half2 constants from int zero and float scale
__device__ __forceinline__ void mk_zs(int z, float s, uint32_t& z2, uint32_t& s2) {
    z2 = 0x64006400u | (unsigned)z | ((unsigned)z << 16);
    unsigned hb = __half_as_ushort(__float2half_rn(s));
    s2 = hb | (hb << 16);
}
__device__ __forceinline__ void mma16(float* d, const uint32_t* a, const uint32_t* b) {
    asm volatile("mma.sync.aligned.m16n8k16.row.col.f32.f16.f16.f32 "
        "{%0,%1,%2,%3},{%4,%5,%6,%7},{%8,%9},{%0,%1,%2,%3};\n"
        : "+f"(d[0]), "+f"(d[1]), "+f"(d[2]), "+f"(d[3])
        : "r"(a[0]), "r"(a[1]), "r"(a[2]), "r"(a[3]), "r"(b[0]), "r"(b[1]));
}
__device__ __forceinline__ float silu_mul(float g, float u) {
    return g / (1.f + __expf(-g)) * u;
}

// smem word layout per buffer (8192 words = 32KB), BK=64:
//  A 128x64: [kf4][mf8][plane4][lane32] = 4096 words
//  B gu: 2 sel x [kf4][nf8][r2][lane32] = 4096 ; B dn: [kf4][nf16][r2][lane32] = 4096
__device__ __forceinline__ int aoffw(int buf, int kf, int mf, int p) {
    return buf * 8192 + ((kf * 8 + mf) * 4 + p) * 32;
}
__device__ __forceinline__ int boffw_gu(int buf, int kf, int nf, int r, int sel) {
    return buf * 8192 + 4096 + sel * 2048 + ((kf * 8 + nf) * 2 + r) * 32;
}
__device__ __forceinline__ int boffw_dn(int buf, int kf, int nf, int r) {
    return buf * 8192 + 4096 + ((kf * 16 + nf) * 2 + r) * 32;
}
#define AUXW 16384
#define SMEM_BYTES ((16384 + 128) * 4)

// ---------------- small kernels ----------------
__global__ void zero_kernel() {
    int i = threadIdx.x;
    if (i < E_) g_counts[i] = 0;
}

__global__ void router_kernel(const float* __restrict__ x, const float* __restrict__ gw) {
    __shared__ float xs[H_];
    __shared__ float part[8][E_];
    __shared__ float scores[E_];
    int t = blockIdx.x;
    for (int h = threadIdx.x; h < H_; h += 256) {
        float v = x[t * H_ + h];
        xs[h] = v;
        g_xh[(size_t)t * H_ + PERM(h)] = __float2half_rn(v);
    }
    __syncthreads();
    int e = threadIdx.x & 31;
    int hh = threadIdx.x >> 5;
    float acc = 0.f;
    for (int h = hh; h < H_; h += 8) acc += xs[h] * gw[h * E_ + e];
    part[hh][e] = acc;
    __syncthreads();
    if (threadIdx.x < E_) {
        float s = 0.f;
        #pragma unroll
        for (int i = 0; i < 8; i++) s += part[i][threadIdx.x];
        scores[threadIdx.x] = 1.f / (1.f + expf(-s));
    }
    __syncthreads();
    if (threadIdx.x == 0) {
        bool used[E_];
        #pragma unroll
        for (int i = 0; i < E_; i++) used[i] = false;
        float v[TOPK]; int id[TOPK];
        float sum = 0.f;
        for (int j = 0; j < TOPK; j++) {
            float best = -1e30f; int bi = 0;
            for (int ee = 0; ee < E_; ee++)
                if (!used[ee] && scores[ee] > best) { best = scores[ee]; bi = ee; }
            used[bi] = true; v[j] = best; id[j] = bi; sum += best;
        }
        float inv = 2.5f / (sum + 1e-20f);
        for (int j = 0; j < TOPK; j++) {
            g_topk_idx[t][j] = id[j];
            g_topk_w[t][j] = v[j] * inv;
            atomicAdd(&g_counts[id[j]], 1);
        }
    }
}

__global__ void scan_scatter_kernel() {
    int tid = threadIdx.x;
    if (tid == 0) {
        int off = 0;
        for (int e = 0; e < E_; e++) {
            g_offsets[e] = off; g_cursor[e] = off; off += g_counts[e];
        }
    }
    __syncthreads();
    int t = tid;
    for (int j = 0; j < TOPK; j++) {
        int e = g_topk_idx[t][j];
        int pos = atomicAdd(&g_cursor[e], 1);
        g_pair_token[pos] = t;
        g_pair_w[pos] = g_topk_w[t][j];
        g_pair_pos[t][j] = pos;
    }
}

// in[R][C] fp32 -> out[C][R] half ; inner (R) index is a K dim -> PERM-stored
__global__ void transpose_half(const float* __restrict__ in, __half* __restrict__ out, int R, int C) {
    __shared__ float tile[32][33];
    int c0 = blockIdx.x * 32, r0 = blockIdx.y * 32;
    for (int i = threadIdx.y; i < 32; i += 8)
        tile[i][threadIdx.x] = in[(size_t)(r0 + i) * C + c0 + threadIdx.x];
    __syncthreads();
    for (int i = threadIdx.y; i < 32; i += 8)
        out[(size_t)(c0 + i) * R + PERM(r0 + threadIdx.x)] = __float2half_rn(tile[threadIdx.x][i]);
}

// ================= expert gate/up: h = silu(X Wg^T) * (X Wu^T) =================
__global__ __launch_bounds__(256, 2) void expert_gu_mma(
    const int* __restrict__ gq, const int* __restrict__ gz, const float* __restrict__ gs,
    const int* __restrict__ uq, const int* __restrict__ uz, const float* __restrict__ us)
{
    extern __shared__ uint32_t smw[];
    int e = blockIdx.z;
    int cnt = g_counts[e];
    int m0 = blockIdx.y * 128;
    if (m0 >= cnt) return;
    int off = g_offsets[e];
    int n0 = blockIdx.x * 64;
    int tid = threadIdx.x;
    uint32_t smb = smem_u32(smw);

    int* toks = (int*)&smw[AUXW];
    if (tid < 128) {
        int m = m0 + tid;
        toks[tid] = (m < cnt) ? g_pair_token[off + m] : 0;
    }
    __syncthreads();

    int fm = tid & 127, kh = tid >> 7;
    const __half* xrow = g_xh + (size_t)toks[fm] * H_ + kh * 32;
    int amf = fm >> 4, ami8 = (fm & 15) >> 3, albA = 4 * (fm & 7);
    uint32_t adst[4];
    #pragma unroll
    for (int gg = 0; gg < 4; gg++)
        adst[gg] = smb + 4 * (aoffw(0, kh * 2 + (gg >> 1), amf, ami8 + 2 * (gg & 1)) + albA);
    int sel = tid >> 7;
    int t2 = tid & 127;
    int fn = t2 & 63, bkh = t2 >> 6;
    long rowb = (long)e * I_ + n0 + fn;
    const int4*  qr4 = (const int4*)((sel ? uq : gq) + rowb * (H_ / 8));
    const int*   zr  = (sel ? uz : gz) + rowb * (H_ / GS_);
    const float* sr  = (sel ? us : gs) + rowb * (H_ / GS_);
    int bnf = fn >> 3, blbB = 4 * (fn & 7);
    int bwi[4];
    #pragma unroll
    for (int wi = 0; wi < 4; wi++)
        bwi[wi] = boffw_gu(0, bkh * 2 + (wi >> 1), bnf, wi & 1, sel) + blbB;

    int w = tid >> 5, lane = tid & 31;
    int wm = w & 3, wn = w >> 2;

    float accG[2][4][4] = {};
    float accU[2][4][4] = {};

    const int NT = H_ / 64;  // 32
    int4 pq; uint32_t pz2, ps2;
    pq = qr4[bkh]; mk_zs(zr[0], sr[0], pz2, ps2);
    #pragma unroll
    for (int gg = 0; gg < 4; gg++) CP16(adst[gg], xrow + gg * 8);
    CP_COMMIT();
    {
        unsigned wd[4] = {(unsigned)pq.x, (unsigned)pq.y, (unsigned)pq.z, (unsigned)pq.w};
        #pragma unroll
        for (int wi = 0; wi < 4; wi++) *(uint4*)&smw[bwi[wi]] = dqw_h(wd[wi], pz2, ps2);
    }
    pq = qr4[2 + bkh];  // next tile, same group (gi=0)
    CP_WAIT0();
    __syncthreads();

    for (int t = 0; t < NT; t++) {
        int buf = t & 1;
        int wo = (buf ^ 1) * 8192;
        uint32_t bo = (buf ^ 1) * 32768;
        if (t + 1 < NT) {
            const __half* xs = xrow + (t + 1) * 64;
            #pragma unroll
            for (int gg = 0; gg < 4; gg++) CP16(adst[gg] + bo, xs + gg * 8);
            CP_COMMIT();
            unsigned wd[4] = {(unsigned)pq.x, (unsigned)pq.y, (unsigned)pq.z, (unsigned)pq.w};
            #pragma unroll
            for (int wi = 0; wi < 4; wi++) *(uint4*)&smw[bwi[wi] + wo] = dqw_h(wd[wi], pz2, ps2);
            int tn = (t + 2 < NT) ? (t + 2) : (NT - 1);
            int gi = tn >> 1;
            pq = qr4[tn * 2 + bkh]; mk_zs(zr[gi], sr[gi], pz2, ps2);
        }
        #pragma unroll
        for (int kf = 0; kf < 4; kf++) {
            uint32_t a[2][4], bg[4][2], bu[4][2];
            #pragma unroll
            for (int mf = 0; mf < 2; mf++)
                #pragma unroll
                for (int r = 0; r < 4; r++)
                    a[mf][r] = smw[aoffw(buf, kf, wm * 2 + mf, r) + lane];
            #pragma unroll
            for (int nf = 0; nf < 4; nf++)
                #pragma unroll
                for (int r = 0; r < 2; r++) {
                    bg[nf][r] = smw[boffw_gu(buf, kf, wn * 4 + nf, r, 0) + lane];
                    bu[nf][r] = smw[boffw_gu(buf, kf, wn * 4 + nf, r, 1) + lane];
                }
            #pragma unroll
            for (int mf = 0; mf < 2; mf++)
                #pragma unroll
                for (int nf = 0; nf < 4; nf++) {
                    mma16(accG[mf][nf], a[mf], bg[nf]);
                    mma16(accU[mf][nf], a[mf], bu[nf]);
                }
        }
        if (t + 1 < NT) CP_WAIT0();
        __syncthreads();
    }

    // epilogue: g_h columns are I (K of down GEMM) -> PERM-scatter
    #pragma unroll
    for (int mf = 0; mf < 2; mf++) {
        #pragma unroll
        for (int hh = 0; hh < 2; hh++) {
            int row = wm * 32 + mf * 16 + (lane >> 2) + hh * 8;
            if (m0 + row < cnt) {
                __half* orow = g_h + (size_t)(off + m0 + row) * I_ + n0;
                #pragma unroll
                for (int nf = 0; nf < 4; nf++) {
                    int col = wn * 32 + nf * 8 + (lane & 3) * 2;
                    float vx = silu_mul(accG[mf][nf][hh * 2],     accU[mf][nf][hh * 2]);
                    float vy = silu_mul(accG[mf][nf][hh * 2 + 1], accU[mf][nf][hh * 2 + 1]);
                    int p = PERM(col);
                    orow[p]     = __float2half_rn(vx);
                    orow[p + 2] = __float2half_rn(vy);
                }
            }
        }
    }
}

// ================= expert down: y = pw * (h @ Wd^T) =================
__global__ __launch_bounds__(256, 2) void expert_down_mma(
    const int* __restrict__ dq, const int* __restrict__ dz, const float* __restrict__ ds)
{
    extern __shared__ uint32_t smw[];
    int e = blockIdx.z;
    int cnt = g_counts[e];
    int m0 = blockIdx.y * 128;
    if (m0 >= cnt) return;
    int off = g_offsets[e];
    int n0 = blockIdx.x * 128;
    int tid = threadIdx.x;
    uint32_t smb = smem_u32(smw);

    float* pwv = (float*)&smw[AUXW];
    if (tid < 128) {
        int m = m0 + tid;
        pwv[tid] = (m < cnt) ? g_pair_w[off + m] : 0.f;
    }
    __syncthreads();

    int fm = tid & 127, kh = tid >> 7;
    size_t ar = (size_t)off + ((m0 + fm < cnt) ? (m0 + fm) : 0);
    const __half* hrow = g_h + ar * I_ + kh * 32;
    int amf = fm >> 4, ami8 = (fm & 15) >> 3, albA = 4 * (fm & 7);
    uint32_t adst[4];
    #pragma unroll
    for (int gg = 0; gg < 4; gg++)
        adst[gg] = smb + 4 * (aoffw(0, kh * 2 + (gg >> 1), amf, ami8 + 2 * (gg & 1)) + albA);

    int fn = tid & 127, bkh = tid >> 7;
    long rowb = (long)e * H_ + n0 + fn;
    const int4*  qr4 = (const int4*)(dq + rowb * (I_ / 8));
    const int*   zr  = dz + rowb * (I_ / GS_);
    const float* sr  = ds + rowb * (I_ / GS_);
    int bnf = fn >> 3, blbB = 4 * (fn & 7);
    int bwi[4];
    #pragma unroll
    for (int wi = 0; wi < 4; wi++)
        bwi[wi] = boffw_dn(0, bkh * 2 + (wi >> 1), bnf, wi & 1) + blbB;

    int w = tid >> 5, lane = tid & 31;
    int wm = w & 1, wn = w >> 1;

    float acc[4][4][4] = {};

    const int NT = I_ / 64;  // 22
    int4 pq; uint32_t pz2, ps2;
    pq = qr4[bkh]; mk_zs(zr[0], sr[0], pz2, ps2);
    #pragma unroll
    for (int gg = 0; gg < 4; gg++) CP16(adst[gg], hrow + gg * 8);
    CP_COMMIT();
    {
        unsigned wd[4] = {(unsigned)pq.x, (unsigned)pq.y, (unsigned)pq.z, (unsigned)pq.w};
        #pragma unroll
        for (int wi = 0; wi < 4; wi++) *(uint4*)&smw[bwi[wi]] = dqw_h(wd[wi], pz2, ps2);
    }
    pq = qr4[2 + bkh];
    CP_WAIT0();
    __syncthreads();

    for (int t = 0; t < NT; t++) {
        int buf = t & 1;
        int wo = (buf ^ 1) * 8192;
        uint32_t bo = (buf ^ 1) * 32768;
        if (t + 1 < NT) {
            const __half* hs = hrow + (t + 1) * 64;
            #pragma unroll
            for (int gg = 0; gg < 4; gg++) CP16(adst[gg] + bo, hs + gg * 8);
            CP_COMMIT();
            unsigned wd[4] = {(unsigned)pq.x, (unsigned)pq.y, (unsigned)pq.z, (unsigned)pq.w};
            #pragma unroll
            for (int wi = 0; wi < 4; wi++) *(uint4*)&smw[bwi[wi] + wo] = dqw_h(wd[wi], pz2, ps2);
            int tn = (t + 2 < NT) ? (t + 2) : (NT - 1);
            int gi = (tn * 64) / GS_;
            pq = qr4[tn * 2 + bkh]; mk_zs(zr[gi], sr[gi], pz2, ps2);
        }
        #pragma unroll
        for (int kf = 0; kf < 4; kf++) {
            uint32_t a[4][4], b[4][2];
            #pragma unroll
            for (int mf = 0; mf < 4; mf++)
                #pragma unroll
                for (int r = 0; r < 4; r++)
                    a[mf][r] = smw[aoffw(buf, kf, wm * 4 + mf, r) + lane];
            #pragma unroll
            for (int nf = 0; nf < 4; nf++)
                #pragma unroll
                for (int r = 0; r < 2; r++)
                    b[nf][r] = smw[boffw_dn(buf, kf, wn * 4 + nf, r) + lane];
            #pragma unroll
            for (int mf = 0; mf < 4; mf++)
                #pragma unroll
                for (int nf = 0; nf < 4; nf++)
                    mma16(acc[mf][nf], a[mf], b[nf]);
        }
        if (t + 1 < NT) CP_WAIT0();
        __syncthreads();
    }

    #pragma unroll
    for (int mf = 0; mf < 4; mf++) {
        #pragma unroll
        for (int hh = 0; hh < 2; hh++) {
            int row = wm * 64 + mf * 16 + (lane >> 2) + hh * 8;
            if (m0 + row < cnt) {
                float wgt = pwv[row];
                float* orow = g_y + (size_t)(off + m0 + row) * H_ + n0;
                #pragma unroll
                for (int nf = 0; nf < 4; nf++) {
                    int col = wn * 32 + nf * 8 + (lane & 3) * 2;
                    float2 v;
                    v.x = wgt * acc[mf][nf][hh * 2];
                    v.y = wgt * acc[mf][nf][hh * 2 + 1];
                    *(float2*)(orow + col) = v;
                }
            }
        }
    }
}

// ================= shared gate/up =================
__global__ __launch_bounds__(256, 2) void shared_gu_mma()
{
    extern __shared__ uint32_t smw[];
    int m0 = blockIdx.y * 128;
    int n0 = blockIdx.x * 64;
    int tid = threadIdx.x;
    uint32_t smb = smem_u32(smw);

    int fm = tid & 127, kh = tid >> 7;
    const __half* xrow = g_xh + (size_t)(m0 + fm) * H_ + kh * 32;
    int amf = fm >> 4, ami8 = (fm & 15) >> 3, albA = 4 * (fm & 7);
    uint32_t adst[4];
    #pragma unroll
    for (int gg = 0; gg < 4; gg++)
        adst[gg] = smb + 4 * (aoffw(0, kh * 2 + (gg >> 1), amf, ami8 + 2 * (gg & 1)) + albA);

    int sel = tid >> 7;
    int t2 = tid & 127;
    int fn = t2 & 63, bkh = t2 >> 6;
    const __half* brow = (sel ? g_suwT : g_sgwT) + (size_t)(n0 + fn) * H_ + bkh * 32;
    int bnf = fn >> 3, blbB = 4 * (fn & 7);
    uint32_t bdst[4];
    #pragma unroll
    for (int wi = 0; wi < 4; wi++)
        bdst[wi] = smb + 4 * (boffw_gu(0, bkh * 2 + (wi >> 1), bnf, wi & 1, sel) + blbB);

    int w = tid >> 5, lane = tid & 31;
    int wm = w & 3, wn = w >> 2;

    float accG[2][4][4] = {};
    float accU[2][4][4] = {};

    const int NT = H_ / 64;  // 32
    #pragma unroll
    for (int gg = 0; gg < 4; gg++) {
        CP16(adst[gg], xrow + gg * 8);
        CP16(bdst[gg], brow + gg * 8);
    }
    CP_COMMIT();
    CP_WAIT0();
    __syncthreads();

    for (int t = 0; t < NT; t++) {
        int buf = t & 1;
        uint32_t bo = (buf ^ 1) * 32768;
        if (t + 1 < NT) {
            const __half* xs = xrow + (t + 1) * 64;
            const __half* bs = brow + (t + 1) * 64;
            #pragma unroll
            for (int gg = 0; gg < 4; gg++) {
                CP16(adst[gg] + bo, xs + gg * 8);
                CP16(bdst[gg] + bo, bs + gg * 8);
            }
            CP_COMMIT();
        }
        #pragma unroll
        for (int kf = 0; kf < 4; kf++) {
            uint32_t a[2][4], bg[4][2], bu[4][2];
            #pragma unroll
            for (int mf = 0; mf < 2; mf++)
                #pragma unroll
                for (int r = 0; r < 4; r++)
                    a[mf][r] = smw[aoffw(buf, kf, wm * 2 + mf, r) + lane];
            #pragma unroll
            for (int nf = 0; nf < 4; nf++)
                #pragma unroll
                for (int r = 0; r < 2; r++) {
                    bg[nf][r] = smw[boffw_gu(buf, kf, wn * 4 + nf, r, 0) + lane];
                    bu[nf][r] = smw[boffw_gu(buf, kf, wn * 4 + nf, r, 1) + lane];
                }
            #pragma unroll
            for (int mf = 0; mf < 2; mf++)
                #pragma unroll
                for (int nf = 0; nf < 4; nf++) {
                    mma16(accG[mf][nf], a[mf], bg[nf]);
                    mma16(accU[mf][nf], a[mf], bu[nf]);
                }
        }
        if (t + 1 < NT) CP_WAIT0();
        __syncthreads();
    }

    // epilogue: g_sh columns are ISH (K of shared-down GEMM) -> PERM-scatter
    #pragma unroll
    for (int mf = 0; mf < 2; mf++) {
        #pragma unroll
        for (int hh = 0; hh < 2; hh++) {
            int row = wm * 32 + mf * 16 + (lane >> 2) + hh * 8;
            __half* orow = g_sh + (size_t)(m0 + row) * ISH_ + n0;
            #pragma unroll
            for (int nf = 0; nf < 4; nf++) {
                int col = wn * 32 + nf * 8 + (lane & 3) * 2;
                float vx = silu_mul(accG[mf][nf][hh * 2],     accU[mf][nf][hh * 2]);
                float vy = silu_mul(accG[mf][nf][hh * 2 + 1], accU[mf][nf][hh * 2 + 1]);
                int p = PERM(col);
                orow[p]     = __float2half_rn(vx);
                orow[p + 2] = __float2half_rn(vy);
            }
        }
    }
}

// ================= shared down + final combine =================
__global__ __launch_bounds__(256, 2) void shared_down_mma(float* __restrict__ out)
{
    extern __shared__ uint32_t smw[];
    int m0 = blockIdx.y * 128;
    int n0 = blockIdx.x * 128;
    int tid = threadIdx.x;
    uint32_t smb = smem_u32(smw);

    int fm = tid & 127, kh = tid >> 7;
    const __half* arow = g_sh + (size_t)(m0 + fm) * ISH_ + kh * 32;
    int amf = fm >> 4, ami8 = (fm & 15) >> 3, albA = 4 * (fm & 7);
    uint32_t adst[4];
    #pragma unroll
    for (int gg = 0; gg < 4; gg++)
        adst[gg] = smb + 4 * (aoffw(0, kh * 2 + (gg >> 1), amf, ami8 + 2 * (gg & 1)) + albA);

    int fn = tid & 127, bkh = tid >> 7;
    const __half* brow = g_sdwT + (size_t)(n0 + fn) * ISH_ + bkh * 32;
    int bnf = fn >> 3, blbB = 4 * (fn & 7);
    uint32_t bdst[4];
    #pragma unroll
    for (int wi = 0; wi < 4; wi++)
        bdst[wi] = smb + 4 * (boffw_dn(0, bkh * 2 + (wi >> 1), bnf, wi & 1) + blbB);

    int w = tid >> 5, lane = tid & 31;
    int wm = w & 1, wn = w >> 1;

    float acc[4][4][4] = {};

    const int NT = ISH_ / 64;  // 44
    #pragma unroll
    for (int gg = 0; gg < 4; gg++) {
        CP16(adst[gg], arow + gg * 8);
        CP16(bdst[gg], brow + gg * 8);
    }
    CP_COMMIT();
    CP_WAIT0();
    __syncthreads();

    for (int t = 0; t < NT; t++) {
        int buf = t & 1;
        uint32_t bo = (buf ^ 1) * 32768;
        if (t + 1 < NT) {
            const __half* as = arow + (t + 1) * 64;
            const __half* bs = brow + (t + 1) * 64;
            #pragma unroll
            for (int gg = 0; gg < 4; gg++) {
                CP16(adst[gg] + bo, as + gg * 8);
                CP16(bdst[gg] + bo, bs + gg * 8);
            }
            CP_COMMIT();
        }
        #pragma unroll
        for (int kf = 0; kf < 4; kf++) {
            uint32_t a[4][4], b[4][2];
            #pragma unroll
            for (int mf = 0; mf < 4; mf++)
                #pragma unroll
                for (int r = 0; r < 4; r++)
                    a[mf][r] = smw[aoffw(buf, kf, wm * 4 + mf, r) + lane];
            #pragma unroll
            for (int nf = 0; nf < 4; nf++)
                #pragma unroll
                for (int r = 0; r < 2; r++)
                    b[nf][r] = smw[boffw_dn(buf, kf, wn * 4 + nf, r) + lane];
            #pragma unroll
            for (int mf = 0; mf < 4; mf++)
                #pragma unroll
                for (int nf = 0; nf < 4; nf++)
                    mma16(acc[mf][nf], a[mf], b[nf]);
        }
        if (t + 1 < NT) CP_WAIT0();
        __syncthreads();
    }

    #pragma unroll
    for (int mf = 0; mf < 4; mf++) {
        #pragma unroll
        for (int hh = 0; hh < 2; hh++) {
            int row = wm * 64 + mf * 16 + (lane >> 2) + hh * 8;
            int tk = m0 + row;
            int p0 = g_pair_pos[tk][0], p1 = g_pair_pos[tk][1];
            int p2 = g_pair_pos[tk][2], p3 = g_pair_pos[tk][3];
            float* orow = out + (size_t)tk * H_ + n0;
            #pragma unroll
            for (int nf = 0; nf < 4; nf++) {
                int col = wn * 32 + nf * 8 + (lane & 3) * 2;
                float2 y0 = *(const float2*)(g_y + (size_t)p0 * H_ + n0 + col);
                float2 y1 = *(const float2*)(g_y + (size_t)p1 * H_ + n0 + col);
                float2 y2 = *(const float2*)(g_y + (size_t)p2 * H_ + n0 + col);
                float2 y3 = *(const float2*)(g_y + (size_t)p3 * H_ + n0 + col);
                float2 v;
                v.x = acc[mf][nf][hh * 2]     + y0.x + y1.x + y2.x + y3.x;
                v.y = acc[mf][nf][hh * 2 + 1] + y0.y + y1.y + y2.y + y3.y;
                *(float2*)(orow + col) = v;
            }
        }
    }
}

// ---------------- launch ----------------
extern "C" void kernel_launch(void* const* d_in, const int* in_sizes, int n_in,
                              void* d_out, int out_size)
{
    const float* x   = (const float*)d_in[0];
    const float* gw  = (const float*)d_in[1];
    const int*   gq  = (const int*)  d_in[2];
    const int*   gz  = (const int*)  d_in[3];
    const float* gs  = (const float*)d_in[4];
    const int*   uq  = (const int*)  d_in[5];
    const int*   uz  = (const int*)  d_in[6];
    const float* us  = (const float*)d_in[7];
    const int*   dq  = (const int*)  d_in[8];
    const int*   dz  = (const int*)  d_in[9];
    const float* ds  = (const float*)d_in[10];
    const float* sgw = (const float*)d_in[11];
    const float* suw = (const float*)d_in[12];
    const float* sdw = (const float*)d_in[13];
    float* out = (float*)d_out;

    static bool attr_done = false;
    if (!attr_done) {
        cudaFuncSetAttribute(expert_gu_mma,   cudaFuncAttributeMaxDynamicSharedMemorySize, SMEM_BYTES);
        cudaFuncSetAttribute(expert_down_mma, cudaFuncAttributeMaxDynamicSharedMemorySize, SMEM_BYTES);
        cudaFuncSetAttribute(shared_gu_mma,   cudaFuncAttributeMaxDynamicSharedMemorySize, SMEM_BYTES);
        cudaFuncSetAttribute(shared_down_mma, cudaFuncAttributeMaxDynamicSharedMemorySize, SMEM_BYTES);
        attr_done = true;
    }

    zero_kernel<<<1, 32>>>();
    router_kernel<<<T_, 256>>>(x, gw);
    scan_scatter_kernel<<<1, 1024>>>();

    dim3 ggu(I_ / 64, T_ / 128, E_);       // (22, 8, 32)
    expert_gu_mma<<<ggu, 256, SMEM_BYTES>>>(gq, gz, gs, uq, uz, us);

    dim3 gdn(H_ / 128, T_ / 128, E_);      // (16, 8, 32)
    expert_down_mma<<<gdn, 256, SMEM_BYTES>>>(dq, dz, ds);

    __half* sgwT; cudaGetSymbolAddress((void**)&sgwT, g_sgwT);
    __half* suwT; cudaGetSymbolAddress((void**)&suwT, g_suwT);
    __half* sdwT; cudaGetSymbolAddress((void**)&sdwT, g_sdwT);
    transpose_half<<<dim3(ISH_ / 32, H_ / 32), dim3(32, 8)>>>(sgw, sgwT, H_, ISH_);
    transpose_half<<<dim3(ISH_ / 32, H_ / 32), dim3(32, 8)>>>(suw, suwT, H_, ISH_);
    transpose_half<<<dim3(H_ / 32, ISH_ / 32), dim3(32, 8)>>>(sdw, sdwT, ISH_, H_);

    dim3 gsg(ISH_ / 64, T_ / 128);         // (44, 8)
    shared_gu_mma<<<gsg, 256, SMEM_BYTES>>>();

    dim3 gsd(H_ / 128, T_ / 128);          // (16, 8)
    shared_down_mma<<<gsd, 256, SMEM_BYTES>>>(out);
}